// round 11
// baseline (speedup 1.0000x reference)
#include <cuda_runtime.h>
#include <cuda_fp16.h>
#include <cstddef>
#include <cstdint>

#define Nn 100000
#define Ee 1600000
#define Gg 100
#define NSCAN 98   // ceil(Nn/1024)

typedef unsigned long long ull;

// ---------------- scratch (device globals; no allocation allowed) ----------
__device__ __half g_P[(size_t)Nn * 144];
__device__ __half g_Q[(size_t)Nn * 144];
__device__ float g_m[(size_t)Nn * 32];
__device__ float g_f0[(size_t)Nn * 32];
__device__ float g_f1[(size_t)Nn * 32];
__device__ int g_cnt[Nn];
__device__ int g_off[Nn];
__device__ int g_bsum[NSCAN + 1];
__device__ int g_sI[Ee];
__device__ int g_sJ[Ee];
__device__ float2 g_sAR[Ee];
__device__ float g_gsum[Gg];
__device__ float g_gcnt[Gg];

__device__ __forceinline__ float silu(float v) {
    float e = __expf(-v);
    return __fdividef(v, 1.0f + e);
}

// packed fp16 silu via tanh: silu(v) = u + u*tanh(u), u = v/2
__device__ __forceinline__ __half2 silu2(__half2 v) {
    __half2 u = __hmul2(v, __float2half2_rn(0.5f));
    uint ur = *reinterpret_cast<uint*>(&u);
    uint tr;
    asm("tanh.approx.f16x2 %0, %1;" : "=r"(tr) : "r"(ur));
    __half2 t = *reinterpret_cast<__half2*>(&tr);
    return __hfma2(u, t, u);
}

__device__ __forceinline__ uint32_t smem_u32(const void* p) {
    return (uint32_t)__cvta_generic_to_shared(p);
}

// ---- packed f32x2 helpers (node/pre kernels) --------------------------------
__device__ __forceinline__ ull pk2(float lo, float hi) {
    ull r; asm("mov.b64 %0, {%1, %2};" : "=l"(r) : "f"(lo), "f"(hi)); return r;
}
__device__ __forceinline__ ull splat2(float v) { return pk2(v, v); }
__device__ __forceinline__ void upk2(float& lo, float& hi, ull v) {
    asm("mov.b64 {%0, %1}, %2;" : "=f"(lo), "=f"(hi) : "l"(v));
}
__device__ __forceinline__ ull fma2(ull a, ull b, ull c) {
    ull d; asm("fma.rn.f32x2 %0, %1, %2, %3;" : "=l"(d) : "l"(a), "l"(b), "l"(c)); return d;
}

// ================= counting sort of edges by destination i ==================
__global__ void hist_kernel(const int* __restrict__ ei, int* __restrict__ cnt) {
    int e = blockIdx.x * blockDim.x + threadIdx.x;
    if (e < Ee) atomicAdd(&cnt[ei[Ee + e]], 1);
}

__global__ void scan1_kernel(const int* __restrict__ cnt, int* __restrict__ off,
                             int* __restrict__ bsum) {
    int idx = blockIdx.x * 1024 + threadIdx.x;
    int v = (idx < Nn) ? cnt[idx] : 0;
    int lane = threadIdx.x & 31, warp = threadIdx.x >> 5;
    int s = v;
#pragma unroll
    for (int d = 1; d < 32; d <<= 1) {
        int t = __shfl_up_sync(~0u, s, d);
        if (lane >= d) s += t;
    }
    __shared__ int ws[32];
    if (lane == 31) ws[warp] = s;
    __syncthreads();
    if (warp == 0) {
        int t = ws[lane];
#pragma unroll
        for (int d = 1; d < 32; d <<= 1) {
            int u = __shfl_up_sync(~0u, t, d);
            if (lane >= d) t += u;
        }
        ws[lane] = t;
    }
    __syncthreads();
    int incl = s + ((warp > 0) ? ws[warp - 1] : 0);
    if (idx < Nn) off[idx] = incl - v;
    if (threadIdx.x == 1023) bsum[blockIdx.x] = incl;
}

__global__ void scan2_kernel(int* __restrict__ bsum) {
    if (threadIdx.x == 0) {
        int run = 0;
        for (int b = 0; b < NSCAN; b++) { int t = bsum[b]; bsum[b] = run; run += t; }
    }
}

__global__ void scan3_kernel(int* __restrict__ off, const int* __restrict__ bsum) {
    int idx = blockIdx.x * 1024 + threadIdx.x;
    if (idx < Nn) off[idx] += bsum[blockIdx.x];
}

__global__ void scatter_kernel(const int* __restrict__ ei, const float* __restrict__ ea,
                               const float* __restrict__ pos, int* __restrict__ off,
                               int* __restrict__ sI, int* __restrict__ sJ,
                               float2* __restrict__ sAR) {
    int e = blockIdx.x * blockDim.x + threadIdx.x;
    if (e >= Ee) return;
    int j = ei[e];
    int i = ei[Ee + e];
    float2 pj = reinterpret_cast<const float2*>(pos)[j];
    float2 pi = reinterpret_cast<const float2*>(pos)[i];
    float dx = pj.x - pi.x, dy = pj.y - pi.y;
    int p = atomicAdd(&off[i], 1);
    sI[p] = i;
    sJ[p] = j;
    sAR[p] = make_float2(ea[e], dx * dx + dy * dy);
}

// ---------------- misc -------------------------------------------------------
__global__ void zero_pool_kernel(float* __restrict__ gs, float* __restrict__ gc) {
    int t = threadIdx.x;
    if (t < Gg) { gs[t] = 0.0f; gc[t] = 0.0f; }
}

// ---------------- per-node projection: P = feats@W1[0:FI]+b1, Q = feats@W1[FI:2FI]
template <int FI, int H, int HP>
__global__ void pre_kernel(const float* __restrict__ featsrc, int lds,
                           const float* __restrict__ W1, const float* __restrict__ b1,
                           __half* __restrict__ P, __half* __restrict__ Q) {
    __shared__ float sf[16][FI];
    int n0 = blockIdx.x * 16;
    int t = threadIdx.x;
    for (int idx = t; idx < 16 * FI; idx += blockDim.x)
        sf[idx / FI][idx % FI] = featsrc[(size_t)(n0 + idx / FI) * lds + (idx % FI)];
    __syncthreads();
    int h = t;
    if (h >= HP) return;
    ull pq[16];
    if (h < H) {
        ull init = pk2(b1[h], 0.0f);
#pragma unroll
        for (int u = 0; u < 16; u++) pq[u] = init;
        for (int f = 0; f < FI; f++) {
            ull w = pk2(W1[f * H + h], W1[(FI + f) * H + h]);
#pragma unroll
            for (int u = 0; u < 16; u++)
                pq[u] = fma2(splat2(sf[u][f]), w, pq[u]);
        }
    } else {
#pragma unroll
        for (int u = 0; u < 16; u++) pq[u] = 0;
    }
#pragma unroll
    for (int u = 0; u < 16; u++) {
        float p, q; upk2(p, q, pq[u]);
        P[(size_t)(n0 + u) * HP + h] = __float2half_rn(p);
        Q[(size_t)(n0 + u) * HP + h] = __float2half_rn(q);
    }
}

// ---------------- edge kernel (sorted by i), tensor-core W2 matmul ----------
// s = silu(P_i + Q_j + a*wa + r*wd)  [fp16 tanh-silu, per-thread row -> smem]
// m = silu(S @ W2 + b2)              [HMMA m16n8k16, fp32 accum]
// scatter: red.global.add.v2.f32 into mi
template <int H, int HP>
__global__ void __launch_bounds__(128) edge_kernel(
        const int* __restrict__ sI, const int* __restrict__ sJ,
        const float2* __restrict__ sAR,
        const __half* __restrict__ P, const __half* __restrict__ Q,
        const float* __restrict__ wa, const float* __restrict__ wd,
        const float* __restrict__ W2, const float* __restrict__ b2,
        float* __restrict__ mi) {
    constexpr int SST = HP + 8;      // half stride: conflict-free STS/ldmatrix
    constexpr int KS = HP / 16;      // k16 steps
    constexpr int CH = HP / 8;       // 16B chunks per P/Q row
    __shared__ __align__(16) __half sS[4][32][SST];
    __shared__ __align__(16) __half sBt[32][HP];   // W2 transposed [n][k]
    __shared__ __align__(16) __half sWa[HP];
    __shared__ __align__(16) __half sWd[HP];
    __shared__ float sb2[32];

    int tid = threadIdx.x;
    for (int idx = tid; idx < HP; idx += 128) {
        sWa[idx] = __float2half_rn((idx < H) ? wa[idx] : 0.0f);
        sWd[idx] = __float2half_rn((idx < H) ? wd[idx] : 0.0f);
    }
    for (int idx = tid; idx < 32 * HP; idx += 128) {
        int n = idx / HP, k = idx % HP;
        sBt[n][k] = __float2half_rn((k < H) ? W2[k * 32 + n] : 0.0f);
    }
    if (tid < 32) sb2[tid] = b2[tid];
    __syncthreads();

    int warp = tid >> 5, lane = tid & 31;
    __half* sSh = &sS[warp][0][0];
    int e = blockIdx.x * 128 + warp * 32 + lane;   // Ee % 128 == 0
    int i = sI[e];
    int j = sJ[e];
    float2 ar = sAR[e];
    __half2 a2 = __float2half2_rn(ar.x);
    __half2 r2 = __float2half2_rn(ar.y);

    // ---- phase 1: per-thread row of S (fp16, tanh silu) ----
    const uint4* Pr = reinterpret_cast<const uint4*>(P + (size_t)i * HP);
    const uint4* Qr = reinterpret_cast<const uint4*>(Q + (size_t)j * HP);
    uint4 pv = Pr[0], qv = Qr[0];
#pragma unroll 1
    for (int t = 0; t < CH; t++) {
        uint4 pc = pv, qc = qv;
        if (t + 1 < CH) { pv = Pr[t + 1]; qv = Qr[t + 1]; }
        uint4 wav = reinterpret_cast<const uint4*>(sWa)[t];
        uint4 wdv = reinterpret_cast<const uint4*>(sWd)[t];
        const __half2* ph = reinterpret_cast<const __half2*>(&pc);
        const __half2* qh = reinterpret_cast<const __half2*>(&qc);
        const __half2* wah = reinterpret_cast<const __half2*>(&wav);
        const __half2* wdh = reinterpret_cast<const __half2*>(&wdv);
        uint4 o;
        uint* op = reinterpret_cast<uint*>(&o);
#pragma unroll
        for (int v = 0; v < 4; v++) {
            __half2 hh = __hadd2(ph[v], qh[v]);
            hh = __hfma2(a2, wah[v], hh);
            hh = __hfma2(r2, wdh[v], hh);
            __half2 sv = silu2(hh);
            op[v] = *reinterpret_cast<uint*>(&sv);
        }
        *reinterpret_cast<uint4*>(&sSh[lane * SST + t * 8]) = o;
    }
    __syncwarp();

    // ---- phase 2: HMMA  S[32xHP] @ W2[HPx32] ----
    int nc = (lane & 3) * 2;
    float acc[2][4][4];
#pragma unroll
    for (int mt = 0; mt < 2; mt++)
#pragma unroll
        for (int nt = 0; nt < 4; nt++) {
            acc[mt][nt][0] = sb2[nt * 8 + nc];
            acc[mt][nt][1] = sb2[nt * 8 + nc + 1];
            acc[mt][nt][2] = acc[mt][nt][0];
            acc[mt][nt][3] = acc[mt][nt][1];
        }

#pragma unroll
    for (int k = 0; k < KS; k++) {
        uint bf[4][2];
#pragma unroll
        for (int nt = 0; nt < 4; nt++) {
            bf[nt][0] = *reinterpret_cast<const uint*>(&sBt[(lane >> 2) + nt * 8][k * 16 + nc]);
            bf[nt][1] = *reinterpret_cast<const uint*>(&sBt[(lane >> 2) + nt * 8][k * 16 + nc + 8]);
        }
#pragma unroll
        for (int mt = 0; mt < 2; mt++) {
            uint a0, a1, a2r, a3;
            uint32_t addr = smem_u32(&sSh[(mt * 16 + (lane & 15)) * SST + k * 16 + (lane >> 4) * 8]);
            asm volatile("ldmatrix.sync.aligned.m8n8.x4.shared.b16 {%0,%1,%2,%3}, [%4];"
                         : "=r"(a0), "=r"(a1), "=r"(a2r), "=r"(a3) : "r"(addr));
#pragma unroll
            for (int nt = 0; nt < 4; nt++) {
                asm volatile(
                    "mma.sync.aligned.m16n8k16.row.col.f32.f16.f16.f32 "
                    "{%0,%1,%2,%3}, {%4,%5,%6,%7}, {%8,%9}, {%0,%1,%2,%3};"
                    : "+f"(acc[mt][nt][0]), "+f"(acc[mt][nt][1]),
                      "+f"(acc[mt][nt][2]), "+f"(acc[mt][nt][3])
                    : "r"(a0), "r"(a1), "r"(a2r), "r"(a3),
                      "r"(bf[nt][0]), "r"(bf[nt][1]));
            }
        }
    }

    // ---- phase 3: silu (exact f32) + atomic scatter ----
#pragma unroll
    for (int mt = 0; mt < 2; mt++) {
        int ilo = __shfl_sync(0xffffffffu, i, (lane >> 2) + mt * 16);
        int ihi = __shfl_sync(0xffffffffu, i, (lane >> 2) + 8 + mt * 16);
#pragma unroll
        for (int nt = 0; nt < 4; nt++) {
            float v0 = silu(acc[mt][nt][0]);
            float v1 = silu(acc[mt][nt][1]);
            float v2 = silu(acc[mt][nt][2]);
            float v3 = silu(acc[mt][nt][3]);
            float* d0 = mi + (size_t)ilo * 32 + nt * 8 + nc;
            float* d1 = mi + (size_t)ihi * 32 + nt * 8 + nc;
            asm volatile("red.global.add.v2.f32 [%0], {%1, %2};"
                         :: "l"(d0), "f"(v0), "f"(v1) : "memory");
            asm volatile("red.global.add.v2.f32 [%0], {%1, %2};"
                         :: "l"(d1), "f"(v2), "f"(v3) : "memory");
        }
    }
}

// ---------------- node MLP: feats' = silu([feats, m_i]@nW1+nb1)@nW2+nb2 ------
template <int FI>
__global__ void __launch_bounds__(256) node_kernel(
        const float* __restrict__ featsrc, int lds,
        const float* __restrict__ mi,
        const float* __restrict__ W1, const float* __restrict__ b1,
        const float* __restrict__ W2, const float* __restrict__ b2,
        float* __restrict__ featdst) {
    constexpr int CAT = FI + 32;
    __shared__ float sW1[CAT * 64];
    __shared__ float sW2[64 * 32];
    __shared__ float sb1[64];
    __shared__ float sb2s[32];
    __shared__ float scat[32][CAT];
    __shared__ float sh[32][64];
    int t = threadIdx.x;
    for (int idx = t; idx < CAT * 64; idx += 256) sW1[idx] = W1[idx];
    for (int idx = t; idx < 64 * 32; idx += 256) sW2[idx] = W2[idx];
    if (t < 64) sb1[t] = b1[t];
    if (t < 32) sb2s[t] = b2[t];

    int warp = t >> 5, lane = t & 31;
    int n0 = blockIdx.x * 32 + warp * 4;
#pragma unroll
    for (int u = 0; u < 4; u++) {
        int n = n0 + u;
        for (int idx = lane; idx < CAT; idx += 32)
            scat[warp * 4 + u][idx] = (idx < FI) ? featsrc[(size_t)n * lds + idx]
                                                 : mi[(size_t)n * 32 + (idx - FI)];
    }
    __syncthreads();

    ull h2[4];
    ull binit = pk2(sb1[lane], sb1[lane + 32]);
#pragma unroll
    for (int u = 0; u < 4; u++) h2[u] = binit;
    for (int f = 0; f < CAT; f++) {
        ull w = pk2(sW1[f * 64 + lane], sW1[f * 64 + lane + 32]);
#pragma unroll
        for (int u = 0; u < 4; u++)
            h2[u] = fma2(splat2(scat[warp * 4 + u][f]), w, h2[u]);
    }
#pragma unroll
    for (int u = 0; u < 4; u++) {
        float lo, hi; upk2(lo, hi, h2[u]);
        sh[warp * 4 + u][lane] = silu(lo);
        sh[warp * 4 + u][lane + 32] = silu(hi);
    }
    __syncwarp();

    ull o01 = splat2(sb2s[lane]);
    ull o23 = o01;
    for (int k = 0; k < 64; k++) {
        ull wv = splat2(sW2[k * 32 + lane]);
        ull x01 = pk2(sh[warp * 4 + 0][k], sh[warp * 4 + 1][k]);
        ull x23 = pk2(sh[warp * 4 + 2][k], sh[warp * 4 + 3][k]);
        o01 = fma2(x01, wv, o01);
        o23 = fma2(x23, wv, o23);
    }
    float o0, o1, o2, o3;
    upk2(o0, o1, o01);
    upk2(o2, o3, o23);
    featdst[(size_t)(n0 + 0) * 32 + lane] = o0;
    featdst[(size_t)(n0 + 1) * 32 + lane] = o1;
    featdst[(size_t)(n0 + 2) * 32 + lane] = o2;
    featdst[(size_t)(n0 + 3) * 32 + lane] = o3;
}

// ---------------- pooling ----------------------------------------------------
__global__ void pool_kernel(const float* __restrict__ feats, const int* __restrict__ batch,
                            const float* __restrict__ linW,
                            float* __restrict__ gsum, float* __restrict__ gcnt) {
    __shared__ float sw[32];
    if (threadIdx.x < 32) sw[threadIdx.x] = linW[threadIdx.x];
    __syncthreads();
    int n = blockIdx.x * blockDim.x + threadIdx.x;
    if (n >= Nn) return;
    const float4* fr = reinterpret_cast<const float4*>(feats + (size_t)n * 32);
    const float4* w4 = reinterpret_cast<const float4*>(sw);
    float s = 0.0f;
#pragma unroll
    for (int c4 = 0; c4 < 8; c4++) {
        float4 f = fr[c4];
        float4 w = w4[c4];
        s += f.x * w.x + f.y * w.y + f.z * w.z + f.w * w.w;
    }
    int g = batch[n];
    atomicAdd(&gsum[g], s);
    atomicAdd(&gcnt[g], 1.0f);
}

__global__ void finalize_kernel(const float* __restrict__ gsum, const float* __restrict__ gcnt,
                                const float* __restrict__ linb, float* __restrict__ out) {
    int g = threadIdx.x;
    if (g < Gg) out[g] = gsum[g] / fmaxf(gcnt[g], 1.0f) + linb[0];
}

// ---------------- host launcher ----------------------------------------------
extern "C" void kernel_launch(void* const* d_in, const int* in_sizes, int n_in,
                              void* d_out, int out_size) {
    const float* x = (const float*)d_in[0];
    const int* ei;
    const float* ea;
    const float* pos;
    if (in_sizes[1] == 2 * Ee) {
        ei = (const int*)d_in[1];
        ea = (const float*)d_in[2];
        pos = (const float*)d_in[3];
    } else {
        pos = (const float*)d_in[1];
        ei = (const int*)d_in[2];
        ea = (const float*)d_in[3];
    }
    const int* batch = (const int*)d_in[4];
    const float* W[26];
    for (int k = 0; k < 26; k++) W[k] = (const float*)d_in[5 + k];
    const float* linW = W[24];
    const float* linb = W[25];

    __half *P, *Q;
    float *mi, *f0, *f1, *gs, *gc;
    int *cnt, *off, *bsum, *sI, *sJ;
    float2* sAR;
    cudaGetSymbolAddress((void**)&P, g_P);
    cudaGetSymbolAddress((void**)&Q, g_Q);
    cudaGetSymbolAddress((void**)&mi, g_m);
    cudaGetSymbolAddress((void**)&f0, g_f0);
    cudaGetSymbolAddress((void**)&f1, g_f1);
    cudaGetSymbolAddress((void**)&cnt, g_cnt);
    cudaGetSymbolAddress((void**)&off, g_off);
    cudaGetSymbolAddress((void**)&bsum, g_bsum);
    cudaGetSymbolAddress((void**)&sI, g_sI);
    cudaGetSymbolAddress((void**)&sJ, g_sJ);
    cudaGetSymbolAddress((void**)&sAR, g_sAR);
    cudaGetSymbolAddress((void**)&gs, g_gsum);
    cudaGetSymbolAddress((void**)&gc, g_gcnt);

    const int EB = Ee / 256;    // 6250 (256-thread kernels)
    const int EBT = Ee / 128;   // 12500 (edge tensor kernel, 128 threads)
    const int EBP = 1250;       // probe grid: 160k edges, ~8 blocks/SM
    const int PREB = Nn / 16;   // 6250
    const int NB = Nn / 32;     // 3125
    const int PB = (Nn + 255) / 256;

    // ---- sort edges by destination i (reused by all 3 layers) ----
    cudaMemsetAsync(cnt, 0, Nn * sizeof(int));
    hist_kernel<<<EB, 256>>>(ei, cnt);                 // kernel idx 0
    scan1_kernel<<<NSCAN, 1024>>>(cnt, off, bsum);     // idx 1
    scan2_kernel<<<1, 32>>>(bsum);                     // idx 2

    // ---- PROFILING PROBE (kernel idx 3 = ncu capture slot) ----
    // Small-grid replay of the real H=132 edge kernel on converged sI/sJ/P/Q
    // from the previous graph replay. Writes mi, which is memset before any
    // real use, so output is unaffected. Deliberate ~40us overhead to obtain
    // the first real ncu profile of the dominant kernel.
    edge_kernel<132, 144><<<EBP, 128>>>(sI, sJ, sAR, P, Q,
                                        W[8] + 64 * 132, W[8] + 65 * 132,
                                        W[10], W[11], mi);

    scan3_kernel<<<NSCAN, 1024>>>(off, bsum);          // idx 4
    scatter_kernel<<<EB, 256>>>(ei, ea, pos, off, sI, sJ, sAR);
    zero_pool_kernel<<<1, 128>>>(gs, gc);

    // ---- layer 1: FI=2, H=12 (HP=16) ----
    pre_kernel<2, 12, 16><<<PREB, 32>>>(x, 2, W[0], W[1], P, Q);
    cudaMemsetAsync(mi, 0, (size_t)Nn * 32 * sizeof(float));
    edge_kernel<12, 16><<<EBT, 128>>>(sI, sJ, sAR, P, Q, W[0] + 4 * 12, W[0] + 5 * 12,
                                      W[2], W[3], mi);
    node_kernel<2><<<NB, 256>>>(x, 2, mi, W[4], W[5], W[6], W[7], f0);

    // ---- layer 2: FI=32, H=132 (HP=144) ----
    pre_kernel<32, 132, 144><<<PREB, 160>>>(f0, 32, W[8], W[9], P, Q);
    cudaMemsetAsync(mi, 0, (size_t)Nn * 32 * sizeof(float));
    edge_kernel<132, 144><<<EBT, 128>>>(sI, sJ, sAR, P, Q, W[8] + 64 * 132, W[8] + 65 * 132,
                                        W[10], W[11], mi);
    node_kernel<32><<<NB, 256>>>(f0, 32, mi, W[12], W[13], W[14], W[15], f1);

    // ---- layer 3: FI=32, H=132 (HP=144) ----
    pre_kernel<32, 132, 144><<<PREB, 160>>>(f1, 32, W[16], W[17], P, Q);
    cudaMemsetAsync(mi, 0, (size_t)Nn * 32 * sizeof(float));
    edge_kernel<132, 144><<<EBT, 128>>>(sI, sJ, sAR, P, Q, W[16] + 64 * 132, W[16] + 65 * 132,
                                        W[18], W[19], mi);
    node_kernel<32><<<NB, 256>>>(f1, 32, mi, W[20], W[21], W[22], W[23], f0);

    // ---- pool + head ----
    pool_kernel<<<PB, 256>>>(f0, batch, linW, gs, gc);
    finalize_kernel<<<1, 128>>>(gs, gc, linb, (float*)d_out);
}

// round 12
// speedup vs baseline: 1.0082x; 1.0082x over previous
#include <cuda_runtime.h>
#include <cuda_fp16.h>
#include <cstddef>
#include <cstdint>

#define Nn 100000
#define Ee 1600000
#define Gg 100
#define NSCAN 98   // ceil(Nn/1024)

typedef unsigned long long ull;

// ---------------- scratch (device globals; no allocation allowed) ----------
__device__ __half g_P[(size_t)Nn * 144];
__device__ __half g_Q[(size_t)Nn * 144];
__device__ float g_m[(size_t)Nn * 32];
__device__ float g_f0[(size_t)Nn * 32];
__device__ float g_f1[(size_t)Nn * 32];
__device__ int g_cnt[Nn];
__device__ int g_off[Nn];
__device__ int g_bsum[NSCAN + 1];
__device__ int g_sI[Ee];
__device__ int g_sJ[Ee];
__device__ float2 g_sAR[Ee];
__device__ float g_gsum[Gg];
__device__ float g_gcnt[Gg];

__device__ __forceinline__ float silu(float v) {
    float e = __expf(-v);
    return __fdividef(v, 1.0f + e);
}

// packed fp16 silu via tanh: silu(v) = u + u*tanh(u), u = v/2
__device__ __forceinline__ __half2 silu2(__half2 v) {
    __half2 u = __hmul2(v, __float2half2_rn(0.5f));
    uint ur = *reinterpret_cast<uint*>(&u);
    uint tr;
    asm("tanh.approx.f16x2 %0, %1;" : "=r"(tr) : "r"(ur));
    __half2 t = *reinterpret_cast<__half2*>(&tr);
    return __hfma2(u, t, u);
}

__device__ __forceinline__ uint32_t smem_u32(const void* p) {
    return (uint32_t)__cvta_generic_to_shared(p);
}

// ---- packed f32x2 helpers (node/pre kernels) --------------------------------
__device__ __forceinline__ ull pk2(float lo, float hi) {
    ull r; asm("mov.b64 %0, {%1, %2};" : "=l"(r) : "f"(lo), "f"(hi)); return r;
}
__device__ __forceinline__ ull splat2(float v) { return pk2(v, v); }
__device__ __forceinline__ void upk2(float& lo, float& hi, ull v) {
    asm("mov.b64 {%0, %1}, %2;" : "=f"(lo), "=f"(hi) : "l"(v));
}
__device__ __forceinline__ ull fma2(ull a, ull b, ull c) {
    ull d; asm("fma.rn.f32x2 %0, %1, %2, %3;" : "=l"(d) : "l"(a), "l"(b), "l"(c)); return d;
}

// ================= counting sort of edges by destination i ==================
__global__ void hist_kernel(const int* __restrict__ ei, int* __restrict__ cnt) {
    int e = blockIdx.x * blockDim.x + threadIdx.x;
    if (e < Ee) atomicAdd(&cnt[ei[Ee + e]], 1);
}

__global__ void scan1_kernel(const int* __restrict__ cnt, int* __restrict__ off,
                             int* __restrict__ bsum) {
    int idx = blockIdx.x * 1024 + threadIdx.x;
    int v = (idx < Nn) ? cnt[idx] : 0;
    int lane = threadIdx.x & 31, warp = threadIdx.x >> 5;
    int s = v;
#pragma unroll
    for (int d = 1; d < 32; d <<= 1) {
        int t = __shfl_up_sync(~0u, s, d);
        if (lane >= d) s += t;
    }
    __shared__ int ws[32];
    if (lane == 31) ws[warp] = s;
    __syncthreads();
    if (warp == 0) {
        int t = ws[lane];
#pragma unroll
        for (int d = 1; d < 32; d <<= 1) {
            int u = __shfl_up_sync(~0u, t, d);
            if (lane >= d) t += u;
        }
        ws[lane] = t;
    }
    __syncthreads();
    int incl = s + ((warp > 0) ? ws[warp - 1] : 0);
    if (idx < Nn) off[idx] = incl - v;
    if (threadIdx.x == 1023) bsum[blockIdx.x] = incl;
}

__global__ void scan2_kernel(int* __restrict__ bsum) {
    if (threadIdx.x == 0) {
        int run = 0;
        for (int b = 0; b < NSCAN; b++) { int t = bsum[b]; bsum[b] = run; run += t; }
    }
}

__global__ void scan3_kernel(int* __restrict__ off, const int* __restrict__ bsum) {
    int idx = blockIdx.x * 1024 + threadIdx.x;
    if (idx < Nn) off[idx] += bsum[blockIdx.x];
}

__global__ void scatter_kernel(const int* __restrict__ ei, const float* __restrict__ ea,
                               const float* __restrict__ pos, int* __restrict__ off,
                               int* __restrict__ sI, int* __restrict__ sJ,
                               float2* __restrict__ sAR) {
    int e = blockIdx.x * blockDim.x + threadIdx.x;
    if (e >= Ee) return;
    int j = ei[e];
    int i = ei[Ee + e];
    float2 pj = reinterpret_cast<const float2*>(pos)[j];
    float2 pi = reinterpret_cast<const float2*>(pos)[i];
    float dx = pj.x - pi.x, dy = pj.y - pi.y;
    int p = atomicAdd(&off[i], 1);
    sI[p] = i;
    sJ[p] = j;
    sAR[p] = make_float2(ea[e], dx * dx + dy * dy);
}

// ---------------- misc -------------------------------------------------------
__global__ void zero_pool_kernel(float* __restrict__ gs, float* __restrict__ gc) {
    int t = threadIdx.x;
    if (t < Gg) { gs[t] = 0.0f; gc[t] = 0.0f; }
}

// ---------------- per-node projection: P = feats@W1[0:FI]+b1, Q = feats@W1[FI:2FI]
template <int FI, int H, int HP>
__global__ void pre_kernel(const float* __restrict__ featsrc, int lds,
                           const float* __restrict__ W1, const float* __restrict__ b1,
                           __half* __restrict__ P, __half* __restrict__ Q) {
    __shared__ float sf[16][FI];
    int n0 = blockIdx.x * 16;
    int t = threadIdx.x;
    for (int idx = t; idx < 16 * FI; idx += blockDim.x)
        sf[idx / FI][idx % FI] = featsrc[(size_t)(n0 + idx / FI) * lds + (idx % FI)];
    __syncthreads();
    int h = t;
    if (h >= HP) return;
    ull pq[16];
    if (h < H) {
        ull init = pk2(b1[h], 0.0f);
#pragma unroll
        for (int u = 0; u < 16; u++) pq[u] = init;
        for (int f = 0; f < FI; f++) {
            ull w = pk2(W1[f * H + h], W1[(FI + f) * H + h]);
#pragma unroll
            for (int u = 0; u < 16; u++)
                pq[u] = fma2(splat2(sf[u][f]), w, pq[u]);
        }
    } else {
#pragma unroll
        for (int u = 0; u < 16; u++) pq[u] = 0;
    }
#pragma unroll
    for (int u = 0; u < 16; u++) {
        float p, q; upk2(p, q, pq[u]);
        P[(size_t)(n0 + u) * HP + h] = __float2half_rn(p);
        Q[(size_t)(n0 + u) * HP + h] = __float2half_rn(q);
    }
}

// ---------------- edge kernel (sorted by i), tensor-core W2 matmul ----------
// s = silu(P_i + Q_j + a*wa + r*wd)  [fp16 tanh-silu, per-thread row -> smem]
// m = silu(S @ W2 + b2)              [HMMA m16n8k16, fp32 accum]
// scatter: red.global.add.v2.f32 into mi
template <int H, int HP>
__global__ void __launch_bounds__(128) edge_kernel(
        const int* __restrict__ sI, const int* __restrict__ sJ,
        const float2* __restrict__ sAR,
        const __half* __restrict__ P, const __half* __restrict__ Q,
        const float* __restrict__ wa, const float* __restrict__ wd,
        const float* __restrict__ W2, const float* __restrict__ b2,
        float* __restrict__ mi) {
    constexpr int SST = HP + 8;      // half stride: conflict-free STS/ldmatrix
    constexpr int KS = HP / 16;      // k16 steps
    constexpr int CH = HP / 8;       // 16B chunks per P/Q row
    __shared__ __align__(16) __half sS[4][32][SST];
    __shared__ __align__(16) __half sBt[32][HP];   // W2 transposed [n][k]
    __shared__ __align__(16) __half sWa[HP];
    __shared__ __align__(16) __half sWd[HP];
    __shared__ float sb2[32];

    int tid = threadIdx.x;
    for (int idx = tid; idx < HP; idx += 128) {
        sWa[idx] = __float2half_rn((idx < H) ? wa[idx] : 0.0f);
        sWd[idx] = __float2half_rn((idx < H) ? wd[idx] : 0.0f);
    }
    for (int idx = tid; idx < 32 * HP; idx += 128) {
        int n = idx / HP, k = idx % HP;
        sBt[n][k] = __float2half_rn((k < H) ? W2[k * 32 + n] : 0.0f);
    }
    if (tid < 32) sb2[tid] = b2[tid];
    __syncthreads();

    int warp = tid >> 5, lane = tid & 31;
    __half* sSh = &sS[warp][0][0];
    int e = blockIdx.x * 128 + warp * 32 + lane;   // Ee % 128 == 0
    int i = sI[e];
    int j = sJ[e];
    float2 ar = sAR[e];
    __half2 a2 = __float2half2_rn(ar.x);
    __half2 r2 = __float2half2_rn(ar.y);

    // ---- phase 1: per-thread row of S (fp16, tanh silu) ----
    const uint4* Pr = reinterpret_cast<const uint4*>(P + (size_t)i * HP);
    const uint4* Qr = reinterpret_cast<const uint4*>(Q + (size_t)j * HP);
    uint4 pv = Pr[0], qv = Qr[0];
#pragma unroll 1
    for (int t = 0; t < CH; t++) {
        uint4 pc = pv, qc = qv;
        if (t + 1 < CH) { pv = Pr[t + 1]; qv = Qr[t + 1]; }
        uint4 wav = reinterpret_cast<const uint4*>(sWa)[t];
        uint4 wdv = reinterpret_cast<const uint4*>(sWd)[t];
        const __half2* ph = reinterpret_cast<const __half2*>(&pc);
        const __half2* qh = reinterpret_cast<const __half2*>(&qc);
        const __half2* wah = reinterpret_cast<const __half2*>(&wav);
        const __half2* wdh = reinterpret_cast<const __half2*>(&wdv);
        uint4 o;
        uint* op = reinterpret_cast<uint*>(&o);
#pragma unroll
        for (int v = 0; v < 4; v++) {
            __half2 hh = __hadd2(ph[v], qh[v]);
            hh = __hfma2(a2, wah[v], hh);
            hh = __hfma2(r2, wdh[v], hh);
            __half2 sv = silu2(hh);
            op[v] = *reinterpret_cast<uint*>(&sv);
        }
        *reinterpret_cast<uint4*>(&sSh[lane * SST + t * 8]) = o;
    }
    __syncwarp();

    // ---- phase 2: HMMA  S[32xHP] @ W2[HPx32] ----
    int nc = (lane & 3) * 2;
    float acc[2][4][4];
#pragma unroll
    for (int mt = 0; mt < 2; mt++)
#pragma unroll
        for (int nt = 0; nt < 4; nt++) {
            acc[mt][nt][0] = sb2[nt * 8 + nc];
            acc[mt][nt][1] = sb2[nt * 8 + nc + 1];
            acc[mt][nt][2] = acc[mt][nt][0];
            acc[mt][nt][3] = acc[mt][nt][1];
        }

#pragma unroll
    for (int k = 0; k < KS; k++) {
        uint bf[4][2];
#pragma unroll
        for (int nt = 0; nt < 4; nt++) {
            bf[nt][0] = *reinterpret_cast<const uint*>(&sBt[(lane >> 2) + nt * 8][k * 16 + nc]);
            bf[nt][1] = *reinterpret_cast<const uint*>(&sBt[(lane >> 2) + nt * 8][k * 16 + nc + 8]);
        }
#pragma unroll
        for (int mt = 0; mt < 2; mt++) {
            uint a0, a1, a2r, a3;
            uint32_t addr = smem_u32(&sSh[(mt * 16 + (lane & 15)) * SST + k * 16 + (lane >> 4) * 8]);
            asm volatile("ldmatrix.sync.aligned.m8n8.x4.shared.b16 {%0,%1,%2,%3}, [%4];"
                         : "=r"(a0), "=r"(a1), "=r"(a2r), "=r"(a3) : "r"(addr));
#pragma unroll
            for (int nt = 0; nt < 4; nt++) {
                asm volatile(
                    "mma.sync.aligned.m16n8k16.row.col.f32.f16.f16.f32 "
                    "{%0,%1,%2,%3}, {%4,%5,%6,%7}, {%8,%9}, {%0,%1,%2,%3};"
                    : "+f"(acc[mt][nt][0]), "+f"(acc[mt][nt][1]),
                      "+f"(acc[mt][nt][2]), "+f"(acc[mt][nt][3])
                    : "r"(a0), "r"(a1), "r"(a2r), "r"(a3),
                      "r"(bf[nt][0]), "r"(bf[nt][1]));
            }
        }
    }

    // ---- phase 3: silu (exact f32) + atomic scatter ----
#pragma unroll
    for (int mt = 0; mt < 2; mt++) {
        int ilo = __shfl_sync(0xffffffffu, i, (lane >> 2) + mt * 16);
        int ihi = __shfl_sync(0xffffffffu, i, (lane >> 2) + 8 + mt * 16);
#pragma unroll
        for (int nt = 0; nt < 4; nt++) {
            float v0 = silu(acc[mt][nt][0]);
            float v1 = silu(acc[mt][nt][1]);
            float v2 = silu(acc[mt][nt][2]);
            float v3 = silu(acc[mt][nt][3]);
            float* d0 = mi + (size_t)ilo * 32 + nt * 8 + nc;
            float* d1 = mi + (size_t)ihi * 32 + nt * 8 + nc;
            asm volatile("red.global.add.v2.f32 [%0], {%1, %2};"
                         :: "l"(d0), "f"(v0), "f"(v1) : "memory");
            asm volatile("red.global.add.v2.f32 [%0], {%1, %2};"
                         :: "l"(d1), "f"(v2), "f"(v3) : "memory");
        }
    }
}

// ---------------- node MLP: feats' = silu([feats, m_i]@nW1+nb1)@nW2+nb2 ------
template <int FI>
__global__ void __launch_bounds__(256) node_kernel(
        const float* __restrict__ featsrc, int lds,
        const float* __restrict__ mi,
        const float* __restrict__ W1, const float* __restrict__ b1,
        const float* __restrict__ W2, const float* __restrict__ b2,
        float* __restrict__ featdst) {
    constexpr int CAT = FI + 32;
    __shared__ float sW1[CAT * 64];
    __shared__ float sW2[64 * 32];
    __shared__ float sb1[64];
    __shared__ float sb2s[32];
    __shared__ float scat[32][CAT];
    __shared__ float sh[32][64];
    int t = threadIdx.x;
    for (int idx = t; idx < CAT * 64; idx += 256) sW1[idx] = W1[idx];
    for (int idx = t; idx < 64 * 32; idx += 256) sW2[idx] = W2[idx];
    if (t < 64) sb1[t] = b1[t];
    if (t < 32) sb2s[t] = b2[t];

    int warp = t >> 5, lane = t & 31;
    int n0 = blockIdx.x * 32 + warp * 4;
#pragma unroll
    for (int u = 0; u < 4; u++) {
        int n = n0 + u;
        for (int idx = lane; idx < CAT; idx += 32)
            scat[warp * 4 + u][idx] = (idx < FI) ? featsrc[(size_t)n * lds + idx]
                                                 : mi[(size_t)n * 32 + (idx - FI)];
    }
    __syncthreads();

    ull h2[4];
    ull binit = pk2(sb1[lane], sb1[lane + 32]);
#pragma unroll
    for (int u = 0; u < 4; u++) h2[u] = binit;
    for (int f = 0; f < CAT; f++) {
        ull w = pk2(sW1[f * 64 + lane], sW1[f * 64 + lane + 32]);
#pragma unroll
        for (int u = 0; u < 4; u++)
            h2[u] = fma2(splat2(scat[warp * 4 + u][f]), w, h2[u]);
    }
#pragma unroll
    for (int u = 0; u < 4; u++) {
        float lo, hi; upk2(lo, hi, h2[u]);
        sh[warp * 4 + u][lane] = silu(lo);
        sh[warp * 4 + u][lane + 32] = silu(hi);
    }
    __syncwarp();

    ull o01 = splat2(sb2s[lane]);
    ull o23 = o01;
    for (int k = 0; k < 64; k++) {
        ull wv = splat2(sW2[k * 32 + lane]);
        ull x01 = pk2(sh[warp * 4 + 0][k], sh[warp * 4 + 1][k]);
        ull x23 = pk2(sh[warp * 4 + 2][k], sh[warp * 4 + 3][k]);
        o01 = fma2(x01, wv, o01);
        o23 = fma2(x23, wv, o23);
    }
    float o0, o1, o2, o3;
    upk2(o0, o1, o01);
    upk2(o2, o3, o23);
    featdst[(size_t)(n0 + 0) * 32 + lane] = o0;
    featdst[(size_t)(n0 + 1) * 32 + lane] = o1;
    featdst[(size_t)(n0 + 2) * 32 + lane] = o2;
    featdst[(size_t)(n0 + 3) * 32 + lane] = o3;
}

// ---------------- pooling ----------------------------------------------------
__global__ void pool_kernel(const float* __restrict__ feats, const int* __restrict__ batch,
                            const float* __restrict__ linW,
                            float* __restrict__ gsum, float* __restrict__ gcnt) {
    __shared__ float sw[32];
    if (threadIdx.x < 32) sw[threadIdx.x] = linW[threadIdx.x];
    __syncthreads();
    int n = blockIdx.x * blockDim.x + threadIdx.x;
    if (n >= Nn) return;
    const float4* fr = reinterpret_cast<const float4*>(feats + (size_t)n * 32);
    const float4* w4 = reinterpret_cast<const float4*>(sw);
    float s = 0.0f;
#pragma unroll
    for (int c4 = 0; c4 < 8; c4++) {
        float4 f = fr[c4];
        float4 w = w4[c4];
        s += f.x * w.x + f.y * w.y + f.z * w.z + f.w * w.w;
    }
    int g = batch[n];
    atomicAdd(&gsum[g], s);
    atomicAdd(&gcnt[g], 1.0f);
}

__global__ void finalize_kernel(const float* __restrict__ gsum, const float* __restrict__ gcnt,
                                const float* __restrict__ linb, float* __restrict__ out) {
    int g = threadIdx.x;
    if (g < Gg) out[g] = gsum[g] / fmaxf(gcnt[g], 1.0f) + linb[0];
}

// ---------------- host launcher ----------------------------------------------
extern "C" void kernel_launch(void* const* d_in, const int* in_sizes, int n_in,
                              void* d_out, int out_size) {
    const float* x = (const float*)d_in[0];
    const int* ei;
    const float* ea;
    const float* pos;
    if (in_sizes[1] == 2 * Ee) {
        ei = (const int*)d_in[1];
        ea = (const float*)d_in[2];
        pos = (const float*)d_in[3];
    } else {
        pos = (const float*)d_in[1];
        ei = (const int*)d_in[2];
        ea = (const float*)d_in[3];
    }
    const int* batch = (const int*)d_in[4];
    const float* W[26];
    for (int k = 0; k < 26; k++) W[k] = (const float*)d_in[5 + k];
    const float* linW = W[24];
    const float* linb = W[25];

    __half *P, *Q;
    float *mi, *f0, *f1, *gs, *gc;
    int *cnt, *off, *bsum, *sI, *sJ;
    float2* sAR;
    cudaGetSymbolAddress((void**)&P, g_P);
    cudaGetSymbolAddress((void**)&Q, g_Q);
    cudaGetSymbolAddress((void**)&mi, g_m);
    cudaGetSymbolAddress((void**)&f0, g_f0);
    cudaGetSymbolAddress((void**)&f1, g_f1);
    cudaGetSymbolAddress((void**)&cnt, g_cnt);
    cudaGetSymbolAddress((void**)&off, g_off);
    cudaGetSymbolAddress((void**)&bsum, g_bsum);
    cudaGetSymbolAddress((void**)&sI, g_sI);
    cudaGetSymbolAddress((void**)&sJ, g_sJ);
    cudaGetSymbolAddress((void**)&sAR, g_sAR);
    cudaGetSymbolAddress((void**)&gs, g_gsum);
    cudaGetSymbolAddress((void**)&gc, g_gcnt);

    const int EB = Ee / 256;    // 6250 (256-thread kernels)
    const int EBT = Ee / 128;   // 12500 (edge tensor kernel, 128 threads)
    const int EBP = 592;        // probe grid: 1 full wave at 4 blocks/SM
    const int PREB = Nn / 16;   // 6250
    const int NB = Nn / 32;     // 3125
    const int PB = (Nn + 255) / 256;

    // ---- sort edges by destination i (reused by all 3 layers) ----
    cudaMemsetAsync(cnt, 0, Nn * sizeof(int));
    hist_kernel<<<EB, 256>>>(ei, cnt);                 // kernel idx 0
    scan1_kernel<<<NSCAN, 1024>>>(cnt, off, bsum);     // idx 1
    scan2_kernel<<<1, 32>>>(bsum);                     // idx 2

    // ---- PROFILING PROBE (ncu capture slot) ----
    // Uses RAW edge_index (always valid, random order) so the first
    // invocation — which ncu captures — is performance-representative.
    // i = ei[Ee+e], j = ei[e]; a,r read from g_sAR (valid memory; values
    // irrelevant to timing). Writes mi, memset before real use.
    edge_kernel<132, 144><<<EBP, 128>>>(ei + Ee, ei, sAR, P, Q,
                                        W[8] + 64 * 132, W[8] + 65 * 132,
                                        W[10], W[11], mi);

    scan3_kernel<<<NSCAN, 1024>>>(off, bsum);
    scatter_kernel<<<EB, 256>>>(ei, ea, pos, off, sI, sJ, sAR);
    zero_pool_kernel<<<1, 128>>>(gs, gc);

    // ---- layer 1: FI=2, H=12 (HP=16) ----
    pre_kernel<2, 12, 16><<<PREB, 32>>>(x, 2, W[0], W[1], P, Q);
    cudaMemsetAsync(mi, 0, (size_t)Nn * 32 * sizeof(float));
    edge_kernel<12, 16><<<EBT, 128>>>(sI, sJ, sAR, P, Q, W[0] + 4 * 12, W[0] + 5 * 12,
                                      W[2], W[3], mi);
    node_kernel<2><<<NB, 256>>>(x, 2, mi, W[4], W[5], W[6], W[7], f0);

    // ---- layer 2: FI=32, H=132 (HP=144) ----
    pre_kernel<32, 132, 144><<<PREB, 160>>>(f0, 32, W[8], W[9], P, Q);
    cudaMemsetAsync(mi, 0, (size_t)Nn * 32 * sizeof(float));
    edge_kernel<132, 144><<<EBT, 128>>>(sI, sJ, sAR, P, Q, W[8] + 64 * 132, W[8] + 65 * 132,
                                        W[10], W[11], mi);
    node_kernel<32><<<NB, 256>>>(f0, 32, mi, W[12], W[13], W[14], W[15], f1);

    // ---- layer 3: FI=32, H=132 (HP=144) ----
    pre_kernel<32, 132, 144><<<PREB, 160>>>(f1, 32, W[16], W[17], P, Q);
    cudaMemsetAsync(mi, 0, (size_t)Nn * 32 * sizeof(float));
    edge_kernel<132, 144><<<EBT, 128>>>(sI, sJ, sAR, P, Q, W[16] + 64 * 132, W[16] + 65 * 132,
                                        W[18], W[19], mi);
    node_kernel<32><<<NB, 256>>>(f1, 32, mi, W[20], W[21], W[22], W[23], f0);

    // ---- pool + head ----
    pool_kernel<<<PB, 256>>>(f0, batch, linW, gs, gc);
    finalize_kernel<<<1, 128>>>(gs, gc, linb, (float*)d_out);
}

// round 13
// speedup vs baseline: 1.3447x; 1.3337x over previous
#include <cuda_runtime.h>
#include <cuda_fp16.h>
#include <cstddef>
#include <cstdint>

#define Nn 100000
#define Ee 1600000
#define Gg 100
#define NSCAN 98   // ceil(Nn/1024)

typedef unsigned long long ull;

// ---------------- scratch (device globals; no allocation allowed) ----------
__device__ __half g_P[(size_t)Nn * 144];
__device__ __half g_Q[(size_t)Nn * 144];
__device__ float g_m[(size_t)Nn * 32];
__device__ float g_f0[(size_t)Nn * 32];
__device__ float g_f1[(size_t)Nn * 32];
__device__ __half g_pack[34 * 144];     // W2^T[32][HP] | wa[HP] | wd[HP], fp16
__device__ int g_cnt[Nn];
__device__ int g_off[Nn];
__device__ int g_bsum[NSCAN + 1];
__device__ int g_sI[Ee];
__device__ int g_sJ[Ee];
__device__ float2 g_sAR[Ee];
__device__ float g_gsum[Gg];
__device__ float g_gcnt[Gg];

__device__ __forceinline__ float silu(float v) {
    float e = __expf(-v);
    return __fdividef(v, 1.0f + e);
}

// packed fp16 silu via tanh: silu(v) = u + u*tanh(u), u = v/2
__device__ __forceinline__ __half2 silu2(__half2 v) {
    __half2 u = __hmul2(v, __float2half2_rn(0.5f));
    uint ur = *reinterpret_cast<uint*>(&u);
    uint tr;
    asm("tanh.approx.f16x2 %0, %1;" : "=r"(tr) : "r"(ur));
    __half2 t = *reinterpret_cast<__half2*>(&tr);
    return __hfma2(u, t, u);
}

__device__ __forceinline__ uint32_t smem_u32(const void* p) {
    return (uint32_t)__cvta_generic_to_shared(p);
}

// ---- packed f32x2 helpers (node/pre kernels) --------------------------------
__device__ __forceinline__ ull pk2(float lo, float hi) {
    ull r; asm("mov.b64 %0, {%1, %2};" : "=l"(r) : "f"(lo), "f"(hi)); return r;
}
__device__ __forceinline__ ull splat2(float v) { return pk2(v, v); }
__device__ __forceinline__ void upk2(float& lo, float& hi, ull v) {
    asm("mov.b64 {%0, %1}, %2;" : "=f"(lo), "=f"(hi) : "l"(v));
}
__device__ __forceinline__ ull fma2(ull a, ull b, ull c) {
    ull d; asm("fma.rn.f32x2 %0, %1, %2, %3;" : "=l"(d) : "l"(a), "l"(b), "l"(c)); return d;
}

// ================= counting sort of edges by destination i ==================
__global__ void hist_kernel(const int* __restrict__ ei, int* __restrict__ cnt) {
    int e = blockIdx.x * blockDim.x + threadIdx.x;
    if (e < Ee) atomicAdd(&cnt[ei[Ee + e]], 1);
}

__global__ void scan1_kernel(const int* __restrict__ cnt, int* __restrict__ off,
                             int* __restrict__ bsum) {
    int idx = blockIdx.x * 1024 + threadIdx.x;
    int v = (idx < Nn) ? cnt[idx] : 0;
    int lane = threadIdx.x & 31, warp = threadIdx.x >> 5;
    int s = v;
#pragma unroll
    for (int d = 1; d < 32; d <<= 1) {
        int t = __shfl_up_sync(~0u, s, d);
        if (lane >= d) s += t;
    }
    __shared__ int ws[32];
    if (lane == 31) ws[warp] = s;
    __syncthreads();
    if (warp == 0) {
        int t = ws[lane];
#pragma unroll
        for (int d = 1; d < 32; d <<= 1) {
            int u = __shfl_up_sync(~0u, t, d);
            if (lane >= d) t += u;
        }
        ws[lane] = t;
    }
    __syncthreads();
    int incl = s + ((warp > 0) ? ws[warp - 1] : 0);
    if (idx < Nn) off[idx] = incl - v;
    if (threadIdx.x == 1023) bsum[blockIdx.x] = incl;
}

__global__ void scan2_kernel(int* __restrict__ bsum) {
    if (threadIdx.x == 0) {
        int run = 0;
        for (int b = 0; b < NSCAN; b++) { int t = bsum[b]; bsum[b] = run; run += t; }
    }
}

__global__ void scan3_kernel(int* __restrict__ off, const int* __restrict__ bsum) {
    int idx = blockIdx.x * 1024 + threadIdx.x;
    if (idx < Nn) off[idx] += bsum[blockIdx.x];
}

__global__ void scatter_kernel(const int* __restrict__ ei, const float* __restrict__ ea,
                               const float* __restrict__ pos, int* __restrict__ off,
                               int* __restrict__ sI, int* __restrict__ sJ,
                               float2* __restrict__ sAR) {
    int e = blockIdx.x * blockDim.x + threadIdx.x;
    if (e >= Ee) return;
    int j = ei[e];
    int i = ei[Ee + e];
    float2 pj = reinterpret_cast<const float2*>(pos)[j];
    float2 pi = reinterpret_cast<const float2*>(pos)[i];
    float dx = pj.x - pi.x, dy = pj.y - pi.y;
    int p = atomicAdd(&off[i], 1);
    sI[p] = i;
    sJ[p] = j;
    sAR[p] = make_float2(ea[e], dx * dx + dy * dy);
}

// ---------------- misc -------------------------------------------------------
__global__ void zero_pool_kernel(float* __restrict__ gs, float* __restrict__ gc) {
    int t = threadIdx.x;
    if (t < Gg) { gs[t] = 0.0f; gc[t] = 0.0f; }
}

// ---------------- weight pack: W2^T (fp16) + wa + wd, built once per layer ---
__global__ void pack_kernel(const float* __restrict__ wa, const float* __restrict__ wd,
                            const float* __restrict__ W2, int H, int HP,
                            __half* __restrict__ dst) {
    int tot = 34 * HP;
    for (int idx = threadIdx.x; idx < tot; idx += blockDim.x) {
        int n = idx / HP, k = idx % HP;
        float v;
        if (n < 32)       v = (k < H) ? W2[k * 32 + n] : 0.0f;
        else if (n == 32) v = (k < H) ? wa[k] : 0.0f;
        else              v = (k < H) ? wd[k] : 0.0f;
        dst[idx] = __float2half_rn(v);
    }
}

// ---------------- per-node projection: P = feats@W1[0:FI]+b1, Q = feats@W1[FI:2FI]
template <int FI, int H, int HP>
__global__ void pre_kernel(const float* __restrict__ featsrc, int lds,
                           const float* __restrict__ W1, const float* __restrict__ b1,
                           __half* __restrict__ P, __half* __restrict__ Q) {
    __shared__ float sf[16][FI];
    int n0 = blockIdx.x * 16;
    int t = threadIdx.x;
    for (int idx = t; idx < 16 * FI; idx += blockDim.x)
        sf[idx / FI][idx % FI] = featsrc[(size_t)(n0 + idx / FI) * lds + (idx % FI)];
    __syncthreads();
    int h = t;
    if (h >= HP) return;
    ull pq[16];
    if (h < H) {
        ull init = pk2(b1[h], 0.0f);
#pragma unroll
        for (int u = 0; u < 16; u++) pq[u] = init;
        for (int f = 0; f < FI; f++) {
            ull w = pk2(W1[f * H + h], W1[(FI + f) * H + h]);
#pragma unroll
            for (int u = 0; u < 16; u++)
                pq[u] = fma2(splat2(sf[u][f]), w, pq[u]);
        }
    } else {
#pragma unroll
        for (int u = 0; u < 16; u++) pq[u] = 0;
    }
#pragma unroll
    for (int u = 0; u < 16; u++) {
        float p, q; upk2(p, q, pq[u]);
        P[(size_t)(n0 + u) * HP + h] = __float2half_rn(p);
        Q[(size_t)(n0 + u) * HP + h] = __float2half_rn(q);
    }
}

// ---------------- edge kernel (sorted by i), tensor-core W2 matmul ----------
// Weights staged from the fp16 pack with COALESCED uint4 copies (the R5-R12
// per-block uncoalesced W2 transpose was ~200-400us/layer of L1 wavefronts).
template <int H, int HP>
__global__ void __launch_bounds__(128) edge_kernel(
        const int* __restrict__ sI, const int* __restrict__ sJ,
        const float2* __restrict__ sAR,
        const __half* __restrict__ P, const __half* __restrict__ Q,
        const __half* __restrict__ packed, const float* __restrict__ b2,
        float* __restrict__ mi) {
    constexpr int SST = HP + 8;      // half stride: conflict-free STS/ldmatrix
    constexpr int KS = HP / 16;      // k16 steps
    constexpr int CH = HP / 8;       // 16B chunks per P/Q row
    constexpr int PACKN = 34 * HP;   // halfs in the weight pack
    __shared__ __align__(16) __half sS[4][32][SST];
    __shared__ __align__(16) __half sPack[PACKN];  // W2t[32][HP] | wa | wd
    __shared__ float sb2[32];

    int tid = threadIdx.x;
    {
        const uint4* ps = reinterpret_cast<const uint4*>(packed);
        uint4* pd = reinterpret_cast<uint4*>(sPack);
        for (int idx = tid; idx < PACKN / 8; idx += 128) pd[idx] = ps[idx];
    }
    if (tid < 32) sb2[tid] = b2[tid];
    __syncthreads();

    const __half* sBt0 = sPack;               // [32][HP]
    const __half* sWa = sPack + 32 * HP;
    const __half* sWd = sPack + 33 * HP;

    int warp = tid >> 5, lane = tid & 31;
    __half* sSh = &sS[warp][0][0];
    int e = blockIdx.x * 128 + warp * 32 + lane;   // Ee % 128 == 0
    int i = sI[e];
    int j = sJ[e];
    float2 ar = sAR[e];
    __half2 a2 = __float2half2_rn(ar.x);
    __half2 r2 = __float2half2_rn(ar.y);

    // ---- phase 1: per-thread row of S (fp16, tanh silu) ----
    const uint4* Pr = reinterpret_cast<const uint4*>(P + (size_t)i * HP);
    const uint4* Qr = reinterpret_cast<const uint4*>(Q + (size_t)j * HP);
    uint4 pv = Pr[0], qv = Qr[0];
#pragma unroll 1
    for (int t = 0; t < CH; t++) {
        uint4 pc = pv, qc = qv;
        if (t + 1 < CH) { pv = Pr[t + 1]; qv = Qr[t + 1]; }
        uint4 wav = reinterpret_cast<const uint4*>(sWa)[t];
        uint4 wdv = reinterpret_cast<const uint4*>(sWd)[t];
        const __half2* ph = reinterpret_cast<const __half2*>(&pc);
        const __half2* qh = reinterpret_cast<const __half2*>(&qc);
        const __half2* wah = reinterpret_cast<const __half2*>(&wav);
        const __half2* wdh = reinterpret_cast<const __half2*>(&wdv);
        uint4 o;
        uint* op = reinterpret_cast<uint*>(&o);
#pragma unroll
        for (int v = 0; v < 4; v++) {
            __half2 hh = __hadd2(ph[v], qh[v]);
            hh = __hfma2(a2, wah[v], hh);
            hh = __hfma2(r2, wdh[v], hh);
            __half2 sv = silu2(hh);
            op[v] = *reinterpret_cast<uint*>(&sv);
        }
        *reinterpret_cast<uint4*>(&sSh[lane * SST + t * 8]) = o;
    }
    __syncwarp();

    // ---- phase 2: HMMA  S[32xHP] @ W2[HPx32] ----
    int nc = (lane & 3) * 2;
    float acc[2][4][4];
#pragma unroll
    for (int mt = 0; mt < 2; mt++)
#pragma unroll
        for (int nt = 0; nt < 4; nt++) {
            acc[mt][nt][0] = sb2[nt * 8 + nc];
            acc[mt][nt][1] = sb2[nt * 8 + nc + 1];
            acc[mt][nt][2] = acc[mt][nt][0];
            acc[mt][nt][3] = acc[mt][nt][1];
        }

#pragma unroll
    for (int k = 0; k < KS; k++) {
        uint bf[4][2];
#pragma unroll
        for (int nt = 0; nt < 4; nt++) {
            int n = (lane >> 2) + nt * 8;
            bf[nt][0] = *reinterpret_cast<const uint*>(&sBt0[n * HP + k * 16 + nc]);
            bf[nt][1] = *reinterpret_cast<const uint*>(&sBt0[n * HP + k * 16 + nc + 8]);
        }
#pragma unroll
        for (int mt = 0; mt < 2; mt++) {
            uint a0, a1, a2r, a3;
            uint32_t addr = smem_u32(&sSh[(mt * 16 + (lane & 15)) * SST + k * 16 + (lane >> 4) * 8]);
            asm volatile("ldmatrix.sync.aligned.m8n8.x4.shared.b16 {%0,%1,%2,%3}, [%4];"
                         : "=r"(a0), "=r"(a1), "=r"(a2r), "=r"(a3) : "r"(addr));
#pragma unroll
            for (int nt = 0; nt < 4; nt++) {
                asm volatile(
                    "mma.sync.aligned.m16n8k16.row.col.f32.f16.f16.f32 "
                    "{%0,%1,%2,%3}, {%4,%5,%6,%7}, {%8,%9}, {%0,%1,%2,%3};"
                    : "+f"(acc[mt][nt][0]), "+f"(acc[mt][nt][1]),
                      "+f"(acc[mt][nt][2]), "+f"(acc[mt][nt][3])
                    : "r"(a0), "r"(a1), "r"(a2r), "r"(a3),
                      "r"(bf[nt][0]), "r"(bf[nt][1]));
            }
        }
    }

    // ---- phase 3: silu (exact f32) + atomic scatter ----
#pragma unroll
    for (int mt = 0; mt < 2; mt++) {
        int ilo = __shfl_sync(0xffffffffu, i, (lane >> 2) + mt * 16);
        int ihi = __shfl_sync(0xffffffffu, i, (lane >> 2) + 8 + mt * 16);
#pragma unroll
        for (int nt = 0; nt < 4; nt++) {
            float v0 = silu(acc[mt][nt][0]);
            float v1 = silu(acc[mt][nt][1]);
            float v2 = silu(acc[mt][nt][2]);
            float v3 = silu(acc[mt][nt][3]);
            float* d0 = mi + (size_t)ilo * 32 + nt * 8 + nc;
            float* d1 = mi + (size_t)ihi * 32 + nt * 8 + nc;
            asm volatile("red.global.add.v2.f32 [%0], {%1, %2};"
                         :: "l"(d0), "f"(v0), "f"(v1) : "memory");
            asm volatile("red.global.add.v2.f32 [%0], {%1, %2};"
                         :: "l"(d1), "f"(v2), "f"(v3) : "memory");
        }
    }
}

// ---------------- node MLP: feats' = silu([feats, m_i]@nW1+nb1)@nW2+nb2 ------
template <int FI>
__global__ void __launch_bounds__(256) node_kernel(
        const float* __restrict__ featsrc, int lds,
        const float* __restrict__ mi,
        const float* __restrict__ W1, const float* __restrict__ b1,
        const float* __restrict__ W2, const float* __restrict__ b2,
        float* __restrict__ featdst) {
    constexpr int CAT = FI + 32;
    __shared__ float sW1[CAT * 64];
    __shared__ float sW2[64 * 32];
    __shared__ float sb1[64];
    __shared__ float sb2s[32];
    __shared__ float scat[32][CAT];
    __shared__ float sh[32][64];
    int t = threadIdx.x;
    for (int idx = t; idx < CAT * 64; idx += 256) sW1[idx] = W1[idx];
    for (int idx = t; idx < 64 * 32; idx += 256) sW2[idx] = W2[idx];
    if (t < 64) sb1[t] = b1[t];
    if (t < 32) sb2s[t] = b2[t];

    int warp = t >> 5, lane = t & 31;
    int n0 = blockIdx.x * 32 + warp * 4;
#pragma unroll
    for (int u = 0; u < 4; u++) {
        int n = n0 + u;
        for (int idx = lane; idx < CAT; idx += 32)
            scat[warp * 4 + u][idx] = (idx < FI) ? featsrc[(size_t)n * lds + idx]
                                                 : mi[(size_t)n * 32 + (idx - FI)];
    }
    __syncthreads();

    ull h2[4];
    ull binit = pk2(sb1[lane], sb1[lane + 32]);
#pragma unroll
    for (int u = 0; u < 4; u++) h2[u] = binit;
    for (int f = 0; f < CAT; f++) {
        ull w = pk2(sW1[f * 64 + lane], sW1[f * 64 + lane + 32]);
#pragma unroll
        for (int u = 0; u < 4; u++)
            h2[u] = fma2(splat2(scat[warp * 4 + u][f]), w, h2[u]);
    }
#pragma unroll
    for (int u = 0; u < 4; u++) {
        float lo, hi; upk2(lo, hi, h2[u]);
        sh[warp * 4 + u][lane] = silu(lo);
        sh[warp * 4 + u][lane + 32] = silu(hi);
    }
    __syncwarp();

    ull o01 = splat2(sb2s[lane]);
    ull o23 = o01;
    for (int k = 0; k < 64; k++) {
        ull wv = splat2(sW2[k * 32 + lane]);
        ull x01 = pk2(sh[warp * 4 + 0][k], sh[warp * 4 + 1][k]);
        ull x23 = pk2(sh[warp * 4 + 2][k], sh[warp * 4 + 3][k]);
        o01 = fma2(x01, wv, o01);
        o23 = fma2(x23, wv, o23);
    }
    float o0, o1, o2, o3;
    upk2(o0, o1, o01);
    upk2(o2, o3, o23);
    featdst[(size_t)(n0 + 0) * 32 + lane] = o0;
    featdst[(size_t)(n0 + 1) * 32 + lane] = o1;
    featdst[(size_t)(n0 + 2) * 32 + lane] = o2;
    featdst[(size_t)(n0 + 3) * 32 + lane] = o3;
}

// ---------------- pooling ----------------------------------------------------
__global__ void pool_kernel(const float* __restrict__ feats, const int* __restrict__ batch,
                            const float* __restrict__ linW,
                            float* __restrict__ gsum, float* __restrict__ gcnt) {
    __shared__ float sw[32];
    if (threadIdx.x < 32) sw[threadIdx.x] = linW[threadIdx.x];
    __syncthreads();
    int n = blockIdx.x * blockDim.x + threadIdx.x;
    if (n >= Nn) return;
    const float4* fr = reinterpret_cast<const float4*>(feats + (size_t)n * 32);
    const float4* w4 = reinterpret_cast<const float4*>(sw);
    float s = 0.0f;
#pragma unroll
    for (int c4 = 0; c4 < 8; c4++) {
        float4 f = fr[c4];
        float4 w = w4[c4];
        s += f.x * w.x + f.y * w.y + f.z * w.z + f.w * w.w;
    }
    int g = batch[n];
    atomicAdd(&gsum[g], s);
    atomicAdd(&gcnt[g], 1.0f);
}

__global__ void finalize_kernel(const float* __restrict__ gsum, const float* __restrict__ gcnt,
                                const float* __restrict__ linb, float* __restrict__ out) {
    int g = threadIdx.x;
    if (g < Gg) out[g] = gsum[g] / fmaxf(gcnt[g], 1.0f) + linb[0];
}

// ---------------- host launcher ----------------------------------------------
extern "C" void kernel_launch(void* const* d_in, const int* in_sizes, int n_in,
                              void* d_out, int out_size) {
    const float* x = (const float*)d_in[0];
    const int* ei;
    const float* ea;
    const float* pos;
    if (in_sizes[1] == 2 * Ee) {
        ei = (const int*)d_in[1];
        ea = (const float*)d_in[2];
        pos = (const float*)d_in[3];
    } else {
        pos = (const float*)d_in[1];
        ei = (const int*)d_in[2];
        ea = (const float*)d_in[3];
    }
    const int* batch = (const int*)d_in[4];
    const float* W[26];
    for (int k = 0; k < 26; k++) W[k] = (const float*)d_in[5 + k];
    const float* linW = W[24];
    const float* linb = W[25];

    __half *P, *Q, *pk;
    float *mi, *f0, *f1, *gs, *gc;
    int *cnt, *off, *bsum, *sI, *sJ;
    float2* sAR;
    cudaGetSymbolAddress((void**)&P, g_P);
    cudaGetSymbolAddress((void**)&Q, g_Q);
    cudaGetSymbolAddress((void**)&pk, g_pack);
    cudaGetSymbolAddress((void**)&mi, g_m);
    cudaGetSymbolAddress((void**)&f0, g_f0);
    cudaGetSymbolAddress((void**)&f1, g_f1);
    cudaGetSymbolAddress((void**)&cnt, g_cnt);
    cudaGetSymbolAddress((void**)&off, g_off);
    cudaGetSymbolAddress((void**)&bsum, g_bsum);
    cudaGetSymbolAddress((void**)&sI, g_sI);
    cudaGetSymbolAddress((void**)&sJ, g_sJ);
    cudaGetSymbolAddress((void**)&sAR, g_sAR);
    cudaGetSymbolAddress((void**)&gs, g_gsum);
    cudaGetSymbolAddress((void**)&gc, g_gcnt);

    const int EB = Ee / 256;    // 6250 (256-thread kernels)
    const int EBT = Ee / 128;   // 12500 (edge tensor kernel, 128 threads)
    const int PREB = Nn / 16;   // 6250
    const int NB = Nn / 32;     // 3125
    const int PB = (Nn + 255) / 256;

    // ---- sort edges by destination i (reused by all 3 layers) ----
    cudaMemsetAsync(cnt, 0, Nn * sizeof(int));
    hist_kernel<<<EB, 256>>>(ei, cnt);
    scan1_kernel<<<NSCAN, 1024>>>(cnt, off, bsum);
    scan2_kernel<<<1, 32>>>(bsum);
    scan3_kernel<<<NSCAN, 1024>>>(off, bsum);
    scatter_kernel<<<EB, 256>>>(ei, ea, pos, off, sI, sJ, sAR);
    zero_pool_kernel<<<1, 128>>>(gs, gc);

    // ---- layer 1: FI=2, H=12 (HP=16) ----
    pack_kernel<<<1, 256>>>(W[0] + 4 * 12, W[0] + 5 * 12, W[2], 12, 16, pk);
    pre_kernel<2, 12, 16><<<PREB, 32>>>(x, 2, W[0], W[1], P, Q);
    cudaMemsetAsync(mi, 0, (size_t)Nn * 32 * sizeof(float));
    edge_kernel<12, 16><<<EBT, 128>>>(sI, sJ, sAR, P, Q, pk, W[3], mi);
    node_kernel<2><<<NB, 256>>>(x, 2, mi, W[4], W[5], W[6], W[7], f0);

    // ---- layer 2: FI=32, H=132 (HP=144) ----
    pack_kernel<<<1, 256>>>(W[8] + 64 * 132, W[8] + 65 * 132, W[10], 132, 144, pk);
    pre_kernel<32, 132, 144><<<PREB, 160>>>(f0, 32, W[8], W[9], P, Q);
    cudaMemsetAsync(mi, 0, (size_t)Nn * 32 * sizeof(float));
    edge_kernel<132, 144><<<EBT, 128>>>(sI, sJ, sAR, P, Q, pk, W[11], mi);
    node_kernel<32><<<NB, 256>>>(f0, 32, mi, W[12], W[13], W[14], W[15], f1);

    // ---- layer 3: FI=32, H=132 (HP=144) ----
    pack_kernel<<<1, 256>>>(W[16] + 64 * 132, W[16] + 65 * 132, W[18], 132, 144, pk);
    pre_kernel<32, 132, 144><<<PREB, 160>>>(f1, 32, W[16], W[17], P, Q);
    cudaMemsetAsync(mi, 0, (size_t)Nn * 32 * sizeof(float));
    edge_kernel<132, 144><<<EBT, 128>>>(sI, sJ, sAR, P, Q, pk, W[19], mi);
    node_kernel<32><<<NB, 256>>>(f1, 32, mi, W[20], W[21], W[22], W[23], f0);

    // ---- pool + head ----
    pool_kernel<<<PB, 256>>>(f0, batch, linW, gs, gc);
    finalize_kernel<<<1, 128>>>(gs, gc, linb, (float*)d_out);
}

// round 14
// speedup vs baseline: 1.4377x; 1.0692x over previous
#include <cuda_runtime.h>
#include <cuda_fp16.h>
#include <cstddef>
#include <cstdint>

#define Nn 100000
#define Ee 1600000
#define Gg 100
#define NSCAN 98   // ceil(Nn/1024)

typedef unsigned long long ull;

// ---------------- scratch (device globals; no allocation allowed) ----------
__device__ __half g_P[(size_t)Nn * 144];
__device__ __half g_Q[(size_t)Nn * 144];
__device__ float g_m[(size_t)Nn * 32];
__device__ float g_f0[(size_t)Nn * 32];
__device__ float g_f1[(size_t)Nn * 32];
__device__ __half g_pack[34 * 144];     // W2^T[32][HP] | wa[HP] | wd[HP], fp16
__device__ int g_cnt[Nn];
__device__ int g_off[Nn];
__device__ int g_bsum[NSCAN + 1];
__device__ int g_sI[Ee];
__device__ int g_sJ[Ee];
__device__ float2 g_sAR[Ee];
__device__ float g_gsum[Gg];
__device__ float g_gcnt[Gg];

__device__ __forceinline__ float silu(float v) {
    float e = __expf(-v);
    return __fdividef(v, 1.0f + e);
}

// packed fp16 silu via tanh: silu(v) = u + u*tanh(u), u = v/2
__device__ __forceinline__ __half2 silu2(__half2 v) {
    __half2 u = __hmul2(v, __float2half2_rn(0.5f));
    uint ur = *reinterpret_cast<uint*>(&u);
    uint tr;
    asm("tanh.approx.f16x2 %0, %1;" : "=r"(tr) : "r"(ur));
    __half2 t = *reinterpret_cast<__half2*>(&tr);
    return __hfma2(u, t, u);
}

__device__ __forceinline__ uint32_t smem_u32(const void* p) {
    return (uint32_t)__cvta_generic_to_shared(p);
}

// ---- packed f32x2 helpers (node/pre kernels) --------------------------------
__device__ __forceinline__ ull pk2(float lo, float hi) {
    ull r; asm("mov.b64 %0, {%1, %2};" : "=l"(r) : "f"(lo), "f"(hi)); return r;
}
__device__ __forceinline__ ull splat2(float v) { return pk2(v, v); }
__device__ __forceinline__ void upk2(float& lo, float& hi, ull v) {
    asm("mov.b64 {%0, %1}, %2;" : "=f"(lo), "=f"(hi) : "l"(v));
}
__device__ __forceinline__ ull fma2(ull a, ull b, ull c) {
    ull d; asm("fma.rn.f32x2 %0, %1, %2, %3;" : "=l"(d) : "l"(a), "l"(b), "l"(c)); return d;
}

// ================= counting sort of edges by destination i ==================
__global__ void hist_kernel(const int* __restrict__ ei, int* __restrict__ cnt) {
    int e = blockIdx.x * blockDim.x + threadIdx.x;
    if (e < Ee) atomicAdd(&cnt[ei[Ee + e]], 1);
}

__global__ void scan1_kernel(const int* __restrict__ cnt, int* __restrict__ off,
                             int* __restrict__ bsum) {
    int idx = blockIdx.x * 1024 + threadIdx.x;
    int v = (idx < Nn) ? cnt[idx] : 0;
    int lane = threadIdx.x & 31, warp = threadIdx.x >> 5;
    int s = v;
#pragma unroll
    for (int d = 1; d < 32; d <<= 1) {
        int t = __shfl_up_sync(~0u, s, d);
        if (lane >= d) s += t;
    }
    __shared__ int ws[32];
    if (lane == 31) ws[warp] = s;
    __syncthreads();
    if (warp == 0) {
        int t = ws[lane];
#pragma unroll
        for (int d = 1; d < 32; d <<= 1) {
            int u = __shfl_up_sync(~0u, t, d);
            if (lane >= d) t += u;
        }
        ws[lane] = t;
    }
    __syncthreads();
    int incl = s + ((warp > 0) ? ws[warp - 1] : 0);
    if (idx < Nn) off[idx] = incl - v;
    if (threadIdx.x == 1023) bsum[blockIdx.x] = incl;
}

__global__ void scan2_kernel(int* __restrict__ bsum) {
    if (threadIdx.x == 0) {
        int run = 0;
        for (int b = 0; b < NSCAN; b++) { int t = bsum[b]; bsum[b] = run; run += t; }
    }
}

__global__ void scan3_kernel(int* __restrict__ off, const int* __restrict__ bsum) {
    int idx = blockIdx.x * 1024 + threadIdx.x;
    if (idx < Nn) off[idx] += bsum[blockIdx.x];
}

__global__ void scatter_kernel(const int* __restrict__ ei, const float* __restrict__ ea,
                               const float* __restrict__ pos, int* __restrict__ off,
                               int* __restrict__ sI, int* __restrict__ sJ,
                               float2* __restrict__ sAR) {
    int e = blockIdx.x * blockDim.x + threadIdx.x;
    if (e >= Ee) return;
    int j = ei[e];
    int i = ei[Ee + e];
    float2 pj = reinterpret_cast<const float2*>(pos)[j];
    float2 pi = reinterpret_cast<const float2*>(pos)[i];
    float dx = pj.x - pi.x, dy = pj.y - pi.y;
    int p = atomicAdd(&off[i], 1);
    sI[p] = i;
    sJ[p] = j;
    sAR[p] = make_float2(ea[e], dx * dx + dy * dy);
}

// ---------------- misc -------------------------------------------------------
__global__ void zero_pool_kernel(float* __restrict__ gs, float* __restrict__ gc) {
    int t = threadIdx.x;
    if (t < Gg) { gs[t] = 0.0f; gc[t] = 0.0f; }
}

// ---------------- weight pack: W2^T (fp16) + wa + wd, built once per layer ---
__global__ void pack_kernel(const float* __restrict__ wa, const float* __restrict__ wd,
                            const float* __restrict__ W2, int H, int HP,
                            __half* __restrict__ dst) {
    int tot = 34 * HP;
    for (int idx = threadIdx.x; idx < tot; idx += blockDim.x) {
        int n = idx / HP, k = idx % HP;
        float v;
        if (n < 32)       v = (k < H) ? W2[k * 32 + n] : 0.0f;
        else if (n == 32) v = (k < H) ? wa[k] : 0.0f;
        else              v = (k < H) ? wd[k] : 0.0f;
        dst[idx] = __float2half_rn(v);
    }
}

// ---------------- per-node projection: P = feats@W1[0:FI]+b1, Q = feats@W1[FI:2FI]
template <int FI, int H, int HP>
__global__ void pre_kernel(const float* __restrict__ featsrc, int lds,
                           const float* __restrict__ W1, const float* __restrict__ b1,
                           __half* __restrict__ P, __half* __restrict__ Q) {
    __shared__ float sf[16][FI];
    int n0 = blockIdx.x * 16;
    int t = threadIdx.x;
    for (int idx = t; idx < 16 * FI; idx += blockDim.x)
        sf[idx / FI][idx % FI] = featsrc[(size_t)(n0 + idx / FI) * lds + (idx % FI)];
    __syncthreads();
    int h = t;
    if (h >= HP) return;
    ull pq[16];
    if (h < H) {
        ull init = pk2(b1[h], 0.0f);
#pragma unroll
        for (int u = 0; u < 16; u++) pq[u] = init;
        for (int f = 0; f < FI; f++) {
            ull w = pk2(W1[f * H + h], W1[(FI + f) * H + h]);
#pragma unroll
            for (int u = 0; u < 16; u++)
                pq[u] = fma2(splat2(sf[u][f]), w, pq[u]);
        }
    } else {
#pragma unroll
        for (int u = 0; u < 16; u++) pq[u] = 0;
    }
#pragma unroll
    for (int u = 0; u < 16; u++) {
        float p, q; upk2(p, q, pq[u]);
        P[(size_t)(n0 + u) * HP + h] = __float2half_rn(p);
        Q[(size_t)(n0 + u) * HP + h] = __float2half_rn(q);
    }
}

// ---------------- edge kernel (sorted by i), tensor-core W2 matmul ----------
// phase 0: COOPERATIVE row-major cp.async staging of Q rows into the S tile
//          (consecutive lanes load consecutive chunks of the SAME row:
//           ~6 L1 wavefronts/instr instead of 32 with the per-lane-row map)
// phase 1: in-place S = silu(Q + P_i + a*wa + r*wd)   [fp16 tanh-silu]
// phase 2: S @ W2 + b2 via HMMA m16n8k16 (fp32 accum)
// phase 3: silu (exact f32) + red.v2 scatter into mi
template <int H, int HP>
__global__ void __launch_bounds__(128) edge_kernel(
        const int* __restrict__ sI, const int* __restrict__ sJ,
        const float2* __restrict__ sAR,
        const __half* __restrict__ P, const __half* __restrict__ Q,
        const __half* __restrict__ packed, const float* __restrict__ b2,
        float* __restrict__ mi) {
    constexpr int SST = HP + 8;      // half stride: conflict-free STS/ldmatrix
    constexpr int KS = HP / 16;      // k16 steps
    constexpr int CH = HP / 8;       // 16B chunks per P/Q row
    constexpr int PACKN = 34 * HP;   // halfs in the weight pack
    __shared__ __align__(16) __half sS[4][32][SST];
    __shared__ __align__(16) __half sPack[PACKN];  // W2t[32][HP] | wa | wd
    __shared__ float sb2[32];

    int tid = threadIdx.x;
    {
        const uint4* ps = reinterpret_cast<const uint4*>(packed);
        uint4* pd = reinterpret_cast<uint4*>(sPack);
        for (int idx = tid; idx < PACKN / 8; idx += 128) pd[idx] = ps[idx];
    }
    if (tid < 32) sb2[tid] = b2[tid];
    __syncthreads();

    const __half* sBt0 = sPack;               // [32][HP]
    const __half* sWa = sPack + 32 * HP;
    const __half* sWd = sPack + 33 * HP;

    int warp = tid >> 5, lane = tid & 31;
    __half* sSh = &sS[warp][0][0];
    int e = blockIdx.x * 128 + warp * 32 + lane;   // Ee % 128 == 0
    int i = sI[e];
    int j = sJ[e];
    float2 ar = sAR[e];
    __half2 a2 = __float2half2_rn(ar.x);
    __half2 r2 = __float2half2_rn(ar.y);

    // ---- phase 0: cooperative row-major Q staging (32 rows x CH chunks) ----
    {
#pragma unroll 1
        for (int idx = lane; idx < 32 * CH; idx += 32) {
            int row = idx / CH;
            int c = idx - row * CH;
            int jr = __shfl_sync(0xffffffffu, j, row);
            const char* src = reinterpret_cast<const char*>(Q + (size_t)jr * HP) + c * 16;
            uint32_t dst = smem_u32(&sSh[row * SST + c * 8]);
            asm volatile("cp.async.cg.shared.global [%0], [%1], 16;"
                         :: "r"(dst), "l"(src) : "memory");
        }
        asm volatile("cp.async.commit_group;" ::: "memory");
    }

    // P row prefetch (sorted i -> few distinct rows per warp, L1-friendly)
    const uint4* Pr = reinterpret_cast<const uint4*>(P + (size_t)i * HP);
    uint4 pv = Pr[0];
    asm volatile("cp.async.wait_group 0;" ::: "memory");
    __syncwarp();

    // ---- phase 1: in-place S = silu(Q + P + a*wa + r*wd) ----
#pragma unroll 1
    for (int t = 0; t < CH; t++) {
        uint4 pc = pv;
        if (t + 1 < CH) pv = Pr[t + 1];
        uint4 qc = *reinterpret_cast<const uint4*>(&sSh[lane * SST + t * 8]);
        uint4 wav = reinterpret_cast<const uint4*>(sWa)[t];
        uint4 wdv = reinterpret_cast<const uint4*>(sWd)[t];
        const __half2* ph = reinterpret_cast<const __half2*>(&pc);
        const __half2* qh = reinterpret_cast<const __half2*>(&qc);
        const __half2* wah = reinterpret_cast<const __half2*>(&wav);
        const __half2* wdh = reinterpret_cast<const __half2*>(&wdv);
        uint4 o;
        uint* op = reinterpret_cast<uint*>(&o);
#pragma unroll
        for (int v = 0; v < 4; v++) {
            __half2 hh = __hadd2(ph[v], qh[v]);
            hh = __hfma2(a2, wah[v], hh);
            hh = __hfma2(r2, wdh[v], hh);
            __half2 sv = silu2(hh);
            op[v] = *reinterpret_cast<uint*>(&sv);
        }
        *reinterpret_cast<uint4*>(&sSh[lane * SST + t * 8]) = o;
    }
    __syncwarp();

    // ---- phase 2: HMMA  S[32xHP] @ W2[HPx32] ----
    int nc = (lane & 3) * 2;
    float acc[2][4][4];
#pragma unroll
    for (int mt = 0; mt < 2; mt++)
#pragma unroll
        for (int nt = 0; nt < 4; nt++) {
            acc[mt][nt][0] = sb2[nt * 8 + nc];
            acc[mt][nt][1] = sb2[nt * 8 + nc + 1];
            acc[mt][nt][2] = acc[mt][nt][0];
            acc[mt][nt][3] = acc[mt][nt][1];
        }

#pragma unroll
    for (int k = 0; k < KS; k++) {
        uint bf[4][2];
#pragma unroll
        for (int nt = 0; nt < 4; nt++) {
            int n = (lane >> 2) + nt * 8;
            bf[nt][0] = *reinterpret_cast<const uint*>(&sBt0[n * HP + k * 16 + nc]);
            bf[nt][1] = *reinterpret_cast<const uint*>(&sBt0[n * HP + k * 16 + nc + 8]);
        }
#pragma unroll
        for (int mt = 0; mt < 2; mt++) {
            uint a0, a1, a2r, a3;
            uint32_t addr = smem_u32(&sSh[(mt * 16 + (lane & 15)) * SST + k * 16 + (lane >> 4) * 8]);
            asm volatile("ldmatrix.sync.aligned.m8n8.x4.shared.b16 {%0,%1,%2,%3}, [%4];"
                         : "=r"(a0), "=r"(a1), "=r"(a2r), "=r"(a3) : "r"(addr));
#pragma unroll
            for (int nt = 0; nt < 4; nt++) {
                asm volatile(
                    "mma.sync.aligned.m16n8k16.row.col.f32.f16.f16.f32 "
                    "{%0,%1,%2,%3}, {%4,%5,%6,%7}, {%8,%9}, {%0,%1,%2,%3};"
                    : "+f"(acc[mt][nt][0]), "+f"(acc[mt][nt][1]),
                      "+f"(acc[mt][nt][2]), "+f"(acc[mt][nt][3])
                    : "r"(a0), "r"(a1), "r"(a2r), "r"(a3),
                      "r"(bf[nt][0]), "r"(bf[nt][1]));
            }
        }
    }

    // ---- phase 3: silu (exact f32) + atomic scatter ----
#pragma unroll
    for (int mt = 0; mt < 2; mt++) {
        int ilo = __shfl_sync(0xffffffffu, i, (lane >> 2) + mt * 16);
        int ihi = __shfl_sync(0xffffffffu, i, (lane >> 2) + 8 + mt * 16);
#pragma unroll
        for (int nt = 0; nt < 4; nt++) {
            float v0 = silu(acc[mt][nt][0]);
            float v1 = silu(acc[mt][nt][1]);
            float v2 = silu(acc[mt][nt][2]);
            float v3 = silu(acc[mt][nt][3]);
            float* d0 = mi + (size_t)ilo * 32 + nt * 8 + nc;
            float* d1 = mi + (size_t)ihi * 32 + nt * 8 + nc;
            asm volatile("red.global.add.v2.f32 [%0], {%1, %2};"
                         :: "l"(d0), "f"(v0), "f"(v1) : "memory");
            asm volatile("red.global.add.v2.f32 [%0], {%1, %2};"
                         :: "l"(d1), "f"(v2), "f"(v3) : "memory");
        }
    }
}

// ---------------- node MLP: feats' = silu([feats, m_i]@nW1+nb1)@nW2+nb2 ------
template <int FI>
__global__ void __launch_bounds__(256) node_kernel(
        const float* __restrict__ featsrc, int lds,
        const float* __restrict__ mi,
        const float* __restrict__ W1, const float* __restrict__ b1,
        const float* __restrict__ W2, const float* __restrict__ b2,
        float* __restrict__ featdst) {
    constexpr int CAT = FI + 32;
    __shared__ float sW1[CAT * 64];
    __shared__ float sW2[64 * 32];
    __shared__ float sb1[64];
    __shared__ float sb2s[32];
    __shared__ float scat[32][CAT];
    __shared__ float sh[32][64];
    int t = threadIdx.x;
    for (int idx = t; idx < CAT * 64; idx += 256) sW1[idx] = W1[idx];
    for (int idx = t; idx < 64 * 32; idx += 256) sW2[idx] = W2[idx];
    if (t < 64) sb1[t] = b1[t];
    if (t < 32) sb2s[t] = b2[t];

    int warp = t >> 5, lane = t & 31;
    int n0 = blockIdx.x * 32 + warp * 4;
#pragma unroll
    for (int u = 0; u < 4; u++) {
        int n = n0 + u;
        for (int idx = lane; idx < CAT; idx += 32)
            scat[warp * 4 + u][idx] = (idx < FI) ? featsrc[(size_t)n * lds + idx]
                                                 : mi[(size_t)n * 32 + (idx - FI)];
    }
    __syncthreads();

    ull h2[4];
    ull binit = pk2(sb1[lane], sb1[lane + 32]);
#pragma unroll
    for (int u = 0; u < 4; u++) h2[u] = binit;
    for (int f = 0; f < CAT; f++) {
        ull w = pk2(sW1[f * 64 + lane], sW1[f * 64 + lane + 32]);
#pragma unroll
        for (int u = 0; u < 4; u++)
            h2[u] = fma2(splat2(scat[warp * 4 + u][f]), w, h2[u]);
    }
#pragma unroll
    for (int u = 0; u < 4; u++) {
        float lo, hi; upk2(lo, hi, h2[u]);
        sh[warp * 4 + u][lane] = silu(lo);
        sh[warp * 4 + u][lane + 32] = silu(hi);
    }
    __syncwarp();

    ull o01 = splat2(sb2s[lane]);
    ull o23 = o01;
    for (int k = 0; k < 64; k++) {
        ull wv = splat2(sW2[k * 32 + lane]);
        ull x01 = pk2(sh[warp * 4 + 0][k], sh[warp * 4 + 1][k]);
        ull x23 = pk2(sh[warp * 4 + 2][k], sh[warp * 4 + 3][k]);
        o01 = fma2(x01, wv, o01);
        o23 = fma2(x23, wv, o23);
    }
    float o0, o1, o2, o3;
    upk2(o0, o1, o01);
    upk2(o2, o3, o23);
    featdst[(size_t)(n0 + 0) * 32 + lane] = o0;
    featdst[(size_t)(n0 + 1) * 32 + lane] = o1;
    featdst[(size_t)(n0 + 2) * 32 + lane] = o2;
    featdst[(size_t)(n0 + 3) * 32 + lane] = o3;
}

// ---------------- pooling ----------------------------------------------------
__global__ void pool_kernel(const float* __restrict__ feats, const int* __restrict__ batch,
                            const float* __restrict__ linW,
                            float* __restrict__ gsum, float* __restrict__ gcnt) {
    __shared__ float sw[32];
    if (threadIdx.x < 32) sw[threadIdx.x] = linW[threadIdx.x];
    __syncthreads();
    int n = blockIdx.x * blockDim.x + threadIdx.x;
    if (n >= Nn) return;
    const float4* fr = reinterpret_cast<const float4*>(feats + (size_t)n * 32);
    const float4* w4 = reinterpret_cast<const float4*>(sw);
    float s = 0.0f;
#pragma unroll
    for (int c4 = 0; c4 < 8; c4++) {
        float4 f = fr[c4];
        float4 w = w4[c4];
        s += f.x * w.x + f.y * w.y + f.z * w.z + f.w * w.w;
    }
    int g = batch[n];
    atomicAdd(&gsum[g], s);
    atomicAdd(&gcnt[g], 1.0f);
}

__global__ void finalize_kernel(const float* __restrict__ gsum, const float* __restrict__ gcnt,
                                const float* __restrict__ linb, float* __restrict__ out) {
    int g = threadIdx.x;
    if (g < Gg) out[g] = gsum[g] / fmaxf(gcnt[g], 1.0f) + linb[0];
}

// ---------------- host launcher ----------------------------------------------
extern "C" void kernel_launch(void* const* d_in, const int* in_sizes, int n_in,
                              void* d_out, int out_size) {
    const float* x = (const float*)d_in[0];
    const int* ei;
    const float* ea;
    const float* pos;
    if (in_sizes[1] == 2 * Ee) {
        ei = (const int*)d_in[1];
        ea = (const float*)d_in[2];
        pos = (const float*)d_in[3];
    } else {
        pos = (const float*)d_in[1];
        ei = (const int*)d_in[2];
        ea = (const float*)d_in[3];
    }
    const int* batch = (const int*)d_in[4];
    const float* W[26];
    for (int k = 0; k < 26; k++) W[k] = (const float*)d_in[5 + k];
    const float* linW = W[24];
    const float* linb = W[25];

    __half *P, *Q, *pk;
    float *mi, *f0, *f1, *gs, *gc;
    int *cnt, *off, *bsum, *sI, *sJ;
    float2* sAR;
    cudaGetSymbolAddress((void**)&P, g_P);
    cudaGetSymbolAddress((void**)&Q, g_Q);
    cudaGetSymbolAddress((void**)&pk, g_pack);
    cudaGetSymbolAddress((void**)&mi, g_m);
    cudaGetSymbolAddress((void**)&f0, g_f0);
    cudaGetSymbolAddress((void**)&f1, g_f1);
    cudaGetSymbolAddress((void**)&cnt, g_cnt);
    cudaGetSymbolAddress((void**)&off, g_off);
    cudaGetSymbolAddress((void**)&bsum, g_bsum);
    cudaGetSymbolAddress((void**)&sI, g_sI);
    cudaGetSymbolAddress((void**)&sJ, g_sJ);
    cudaGetSymbolAddress((void**)&sAR, g_sAR);
    cudaGetSymbolAddress((void**)&gs, g_gsum);
    cudaGetSymbolAddress((void**)&gc, g_gcnt);

    const int EB = Ee / 256;    // 6250 (256-thread kernels)
    const int EBT = Ee / 128;   // 12500 (edge tensor kernel, 128 threads)
    const int PREB = Nn / 16;   // 6250
    const int NB = Nn / 32;     // 3125
    const int PB = (Nn + 255) / 256;

    // ---- sort edges by destination i (reused by all 3 layers) ----
    cudaMemsetAsync(cnt, 0, Nn * sizeof(int));
    hist_kernel<<<EB, 256>>>(ei, cnt);
    scan1_kernel<<<NSCAN, 1024>>>(cnt, off, bsum);
    scan2_kernel<<<1, 32>>>(bsum);
    scan3_kernel<<<NSCAN, 1024>>>(off, bsum);
    scatter_kernel<<<EB, 256>>>(ei, ea, pos, off, sI, sJ, sAR);
    zero_pool_kernel<<<1, 128>>>(gs, gc);

    // ---- layer 1: FI=2, H=12 (HP=16) ----
    pack_kernel<<<1, 256>>>(W[0] + 4 * 12, W[0] + 5 * 12, W[2], 12, 16, pk);
    pre_kernel<2, 12, 16><<<PREB, 32>>>(x, 2, W[0], W[1], P, Q);
    cudaMemsetAsync(mi, 0, (size_t)Nn * 32 * sizeof(float));
    edge_kernel<12, 16><<<EBT, 128>>>(sI, sJ, sAR, P, Q, pk, W[3], mi);
    node_kernel<2><<<NB, 256>>>(x, 2, mi, W[4], W[5], W[6], W[7], f0);

    // ---- layer 2: FI=32, H=132 (HP=144) ----
    pack_kernel<<<1, 256>>>(W[8] + 64 * 132, W[8] + 65 * 132, W[10], 132, 144, pk);
    pre_kernel<32, 132, 144><<<PREB, 160>>>(f0, 32, W[8], W[9], P, Q);
    cudaMemsetAsync(mi, 0, (size_t)Nn * 32 * sizeof(float));
    edge_kernel<132, 144><<<EBT, 128>>>(sI, sJ, sAR, P, Q, pk, W[11], mi);
    node_kernel<32><<<NB, 256>>>(f0, 32, mi, W[12], W[13], W[14], W[15], f1);

    // ---- layer 3: FI=32, H=132 (HP=144) ----
    pack_kernel<<<1, 256>>>(W[16] + 64 * 132, W[16] + 65 * 132, W[18], 132, 144, pk);
    pre_kernel<32, 132, 144><<<PREB, 160>>>(f1, 32, W[16], W[17], P, Q);
    cudaMemsetAsync(mi, 0, (size_t)Nn * 32 * sizeof(float));
    edge_kernel<132, 144><<<EBT, 128>>>(sI, sJ, sAR, P, Q, pk, W[19], mi);
    node_kernel<32><<<NB, 256>>>(f1, 32, mi, W[20], W[21], W[22], W[23], f0);

    // ---- pool + head ----
    pool_kernel<<<PB, 256>>>(f0, batch, linW, gs, gc);
    finalize_kernel<<<1, 128>>>(gs, gc, linb, (float*)d_out);
}

// round 15
// speedup vs baseline: 1.5399x; 1.0711x over previous
#include <cuda_runtime.h>
#include <cuda_fp16.h>
#include <cstddef>
#include <cstdint>

#define Nn 100000
#define Ee 1600000
#define Gg 100
#define NSCAN 98   // ceil(Nn/1024)

typedef unsigned long long ull;

// ---------------- scratch (device globals; no allocation allowed) ----------
__device__ __half g_P[(size_t)Nn * 144];
__device__ __half g_Q[(size_t)Nn * 144];
__device__ float g_m[(size_t)Nn * 32];
__device__ float g_f0[(size_t)Nn * 32];
__device__ float g_f1[(size_t)Nn * 32];
__device__ __align__(16) __half g_pack[34 * 144];  // W2^T[32][HP] | wa | wd
__device__ int g_cnt[Nn];
__device__ int g_off[Nn];
__device__ int g_bsum[NSCAN + 1];
__device__ int g_sI[Ee];
__device__ int g_sJ[Ee];
__device__ float2 g_sAR[Ee];
__device__ float g_gsum[Gg];
__device__ float g_gcnt[Gg];

__device__ __forceinline__ float silu(float v) {
    float e = __expf(-v);
    return __fdividef(v, 1.0f + e);
}

// packed fp16 silu via tanh: silu(v) = u + u*tanh(u), u = v/2
__device__ __forceinline__ __half2 silu2(__half2 v) {
    __half2 u = __hmul2(v, __float2half2_rn(0.5f));
    uint ur = *reinterpret_cast<uint*>(&u);
    uint tr;
    asm("tanh.approx.f16x2 %0, %1;" : "=r"(tr) : "r"(ur));
    __half2 t = *reinterpret_cast<__half2*>(&tr);
    return __hfma2(u, t, u);
}

__device__ __forceinline__ uint32_t smem_u32(const void* p) {
    return (uint32_t)__cvta_generic_to_shared(p);
}

// ---- packed f32x2 helpers (node/pre kernels) --------------------------------
__device__ __forceinline__ ull pk2(float lo, float hi) {
    ull r; asm("mov.b64 %0, {%1, %2};" : "=l"(r) : "f"(lo), "f"(hi)); return r;
}
__device__ __forceinline__ ull splat2(float v) { return pk2(v, v); }
__device__ __forceinline__ void upk2(float& lo, float& hi, ull v) {
    asm("mov.b64 {%0, %1}, %2;" : "=f"(lo), "=f"(hi) : "l"(v));
}
__device__ __forceinline__ ull fma2(ull a, ull b, ull c) {
    ull d; asm("fma.rn.f32x2 %0, %1, %2, %3;" : "=l"(d) : "l"(a), "l"(b), "l"(c)); return d;
}

// ================= counting sort of edges by destination i ==================
__global__ void hist_kernel(const int* __restrict__ ei, int* __restrict__ cnt) {
    int e = blockIdx.x * blockDim.x + threadIdx.x;
    if (e < Ee) atomicAdd(&cnt[ei[Ee + e]], 1);
}

__global__ void scan1_kernel(const int* __restrict__ cnt, int* __restrict__ off,
                             int* __restrict__ bsum) {
    int idx = blockIdx.x * 1024 + threadIdx.x;
    int v = (idx < Nn) ? cnt[idx] : 0;
    int lane = threadIdx.x & 31, warp = threadIdx.x >> 5;
    int s = v;
#pragma unroll
    for (int d = 1; d < 32; d <<= 1) {
        int t = __shfl_up_sync(~0u, s, d);
        if (lane >= d) s += t;
    }
    __shared__ int ws[32];
    if (lane == 31) ws[warp] = s;
    __syncthreads();
    if (warp == 0) {
        int t = ws[lane];
#pragma unroll
        for (int d = 1; d < 32; d <<= 1) {
            int u = __shfl_up_sync(~0u, t, d);
            if (lane >= d) t += u;
        }
        ws[lane] = t;
    }
    __syncthreads();
    int incl = s + ((warp > 0) ? ws[warp - 1] : 0);
    if (idx < Nn) off[idx] = incl - v;
    if (threadIdx.x == 1023) bsum[blockIdx.x] = incl;
}

__global__ void scan2_kernel(int* __restrict__ bsum) {
    if (threadIdx.x == 0) {
        int run = 0;
        for (int b = 0; b < NSCAN; b++) { int t = bsum[b]; bsum[b] = run; run += t; }
    }
}

__global__ void scan3_kernel(int* __restrict__ off, const int* __restrict__ bsum) {
    int idx = blockIdx.x * 1024 + threadIdx.x;
    if (idx < Nn) off[idx] += bsum[blockIdx.x];
}

__global__ void scatter_kernel(const int* __restrict__ ei, const float* __restrict__ ea,
                               const float* __restrict__ pos, int* __restrict__ off,
                               int* __restrict__ sI, int* __restrict__ sJ,
                               float2* __restrict__ sAR) {
    int e = blockIdx.x * blockDim.x + threadIdx.x;
    if (e >= Ee) return;
    int j = ei[e];
    int i = ei[Ee + e];
    float2 pj = reinterpret_cast<const float2*>(pos)[j];
    float2 pi = reinterpret_cast<const float2*>(pos)[i];
    float dx = pj.x - pi.x, dy = pj.y - pi.y;
    int p = atomicAdd(&off[i], 1);
    sI[p] = i;
    sJ[p] = j;
    sAR[p] = make_float2(ea[e], dx * dx + dy * dy);
}

// ---------------- misc -------------------------------------------------------
__global__ void zero_pool_kernel(float* __restrict__ gs, float* __restrict__ gc) {
    int t = threadIdx.x;
    if (t < Gg) { gs[t] = 0.0f; gc[t] = 0.0f; }
}

// ---------------- weight pack: W2^T (fp16) + wa + wd, built once per layer ---
__global__ void pack_kernel(const float* __restrict__ wa, const float* __restrict__ wd,
                            const float* __restrict__ W2, int H, int HP,
                            __half* __restrict__ dst) {
    int tot = 34 * HP;
    for (int idx = threadIdx.x; idx < tot; idx += blockDim.x) {
        int n = idx / HP, k = idx % HP;
        float v;
        if (n < 32)       v = (k < H) ? W2[k * 32 + n] : 0.0f;
        else if (n == 32) v = (k < H) ? wa[k] : 0.0f;
        else              v = (k < H) ? wd[k] : 0.0f;
        dst[idx] = __float2half_rn(v);
    }
}

// ---------------- per-node projection: P = feats@W1[0:FI]+b1, Q = feats@W1[FI:2FI]
template <int FI, int H, int HP>
__global__ void pre_kernel(const float* __restrict__ featsrc, int lds,
                           const float* __restrict__ W1, const float* __restrict__ b1,
                           __half* __restrict__ P, __half* __restrict__ Q) {
    __shared__ float sf[16][FI];
    int n0 = blockIdx.x * 16;
    int t = threadIdx.x;
    for (int idx = t; idx < 16 * FI; idx += blockDim.x)
        sf[idx / FI][idx % FI] = featsrc[(size_t)(n0 + idx / FI) * lds + (idx % FI)];
    __syncthreads();
    int h = t;
    if (h >= HP) return;
    ull pq[16];
    if (h < H) {
        ull init = pk2(b1[h], 0.0f);
#pragma unroll
        for (int u = 0; u < 16; u++) pq[u] = init;
        for (int f = 0; f < FI; f++) {
            ull w = pk2(W1[f * H + h], W1[(FI + f) * H + h]);
#pragma unroll
            for (int u = 0; u < 16; u++)
                pq[u] = fma2(splat2(sf[u][f]), w, pq[u]);
        }
    } else {
#pragma unroll
        for (int u = 0; u < 16; u++) pq[u] = 0;
    }
#pragma unroll
    for (int u = 0; u < 16; u++) {
        float p, q; upk2(p, q, pq[u]);
        P[(size_t)(n0 + u) * HP + h] = __float2half_rn(p);
        Q[(size_t)(n0 + u) * HP + h] = __float2half_rn(q);
    }
}

// ---------------- edge kernel (sorted by i), tensor-core W2 matmul ----------
// phase 0: cooperative row-major cp.async staging of Q rows into the S tile
// phase 1: in-place S = silu(Q + P_i + a*wa + r*wd)   [fp16 tanh-silu]
// phase 2: S @ W2 + b2 via HMMA m16n8k16 (fp32 accum); sBt stride padded
//          to PST=HP+8 -> conflict-free B-fragment LDS
// phase 3: silu (exact f32) + WARP SEGMENTED MERGE over sorted i (shfl
//          Kogge-Stone suffix sums per 8-row chain), run heads fire red.v2
template <int H, int HP>
__global__ void __launch_bounds__(128) edge_kernel(
        const int* __restrict__ sI, const int* __restrict__ sJ,
        const float2* __restrict__ sAR,
        const __half* __restrict__ P, const __half* __restrict__ Q,
        const __half* __restrict__ packed, const float* __restrict__ b2,
        float* __restrict__ mi) {
    constexpr int SST = HP + 8;      // S-tile half stride
    constexpr int PST = HP + 8;      // sBt half stride (conflict-free B loads)
    constexpr int KS = HP / 16;      // k16 steps
    constexpr int CH = HP / 8;       // 16B chunks per P/Q row
    __shared__ __align__(16) __half sS[4][32][SST];
    __shared__ __align__(16) __half sBt[32 * PST];
    __shared__ __align__(16) __half sWa[HP];
    __shared__ __align__(16) __half sWd[HP];
    __shared__ float sb2[32];

    int tid = threadIdx.x;
    // staged copy of the weight pack (coalesced global reads, remapped stride)
    for (int idx = tid; idx < 32 * CH; idx += 128) {
        int row = idx / CH, c = idx % CH;
        *reinterpret_cast<uint4*>(&sBt[row * PST + c * 8]) =
            *reinterpret_cast<const uint4*>(&packed[row * HP + c * 8]);
    }
    for (int idx = tid; idx < 2 * CH; idx += 128) {
        int w = idx / CH, c = idx % CH;
        __half* dst = w ? sWd : sWa;
        *reinterpret_cast<uint4*>(&dst[c * 8]) =
            *reinterpret_cast<const uint4*>(&packed[(32 + w) * HP + c * 8]);
    }
    if (tid < 32) sb2[tid] = b2[tid];
    __syncthreads();

    int warp = tid >> 5, lane = tid & 31;
    __half* sSh = &sS[warp][0][0];
    int e = blockIdx.x * 128 + warp * 32 + lane;   // Ee % 128 == 0
    int i = sI[e];
    int j = sJ[e];
    float2 ar = sAR[e];
    __half2 a2 = __float2half2_rn(ar.x);
    __half2 r2 = __float2half2_rn(ar.y);

    // ---- phase 0: cooperative row-major Q staging (32 rows x CH chunks) ----
    {
#pragma unroll 1
        for (int idx = lane; idx < 32 * CH; idx += 32) {
            int row = idx / CH;
            int c = idx - row * CH;
            int jr = __shfl_sync(0xffffffffu, j, row);
            const char* src = reinterpret_cast<const char*>(Q + (size_t)jr * HP) + c * 16;
            uint32_t dst = smem_u32(&sSh[row * SST + c * 8]);
            asm volatile("cp.async.cg.shared.global [%0], [%1], 16;"
                         :: "r"(dst), "l"(src) : "memory");
        }
        asm volatile("cp.async.commit_group;" ::: "memory");
    }

    const uint4* Pr = reinterpret_cast<const uint4*>(P + (size_t)i * HP);
    uint4 pv = Pr[0];
    asm volatile("cp.async.wait_group 0;" ::: "memory");
    __syncwarp();

    // ---- phase 1: in-place S = silu(Q + P + a*wa + r*wd) ----
#pragma unroll 1
    for (int t = 0; t < CH; t++) {
        uint4 pc = pv;
        if (t + 1 < CH) pv = Pr[t + 1];
        uint4 qc = *reinterpret_cast<const uint4*>(&sSh[lane * SST + t * 8]);
        uint4 wav = reinterpret_cast<const uint4*>(sWa)[t];
        uint4 wdv = reinterpret_cast<const uint4*>(sWd)[t];
        const __half2* ph = reinterpret_cast<const __half2*>(&pc);
        const __half2* qh = reinterpret_cast<const __half2*>(&qc);
        const __half2* wah = reinterpret_cast<const __half2*>(&wav);
        const __half2* wdh = reinterpret_cast<const __half2*>(&wdv);
        uint4 o;
        uint* op = reinterpret_cast<uint*>(&o);
#pragma unroll
        for (int v = 0; v < 4; v++) {
            __half2 hh = __hadd2(ph[v], qh[v]);
            hh = __hfma2(a2, wah[v], hh);
            hh = __hfma2(r2, wdh[v], hh);
            __half2 sv = silu2(hh);
            op[v] = *reinterpret_cast<uint*>(&sv);
        }
        *reinterpret_cast<uint4*>(&sSh[lane * SST + t * 8]) = o;
    }
    __syncwarp();

    // ---- phase 2: HMMA  S[32xHP] @ W2[HPx32] ----
    int nc = (lane & 3) * 2;
    float acc[2][4][4];
#pragma unroll
    for (int mt = 0; mt < 2; mt++)
#pragma unroll
        for (int nt = 0; nt < 4; nt++) {
            acc[mt][nt][0] = sb2[nt * 8 + nc];
            acc[mt][nt][1] = sb2[nt * 8 + nc + 1];
            acc[mt][nt][2] = acc[mt][nt][0];
            acc[mt][nt][3] = acc[mt][nt][1];
        }

#pragma unroll
    for (int k = 0; k < KS; k++) {
        uint bf[4][2];
#pragma unroll
        for (int nt = 0; nt < 4; nt++) {
            int n = (lane >> 2) + nt * 8;
            bf[nt][0] = *reinterpret_cast<const uint*>(&sBt[n * PST + k * 16 + nc]);
            bf[nt][1] = *reinterpret_cast<const uint*>(&sBt[n * PST + k * 16 + nc + 8]);
        }
#pragma unroll
        for (int mt = 0; mt < 2; mt++) {
            uint a0, a1, a2r, a3;
            uint32_t addr = smem_u32(&sSh[(mt * 16 + (lane & 15)) * SST + k * 16 + (lane >> 4) * 8]);
            asm volatile("ldmatrix.sync.aligned.m8n8.x4.shared.b16 {%0,%1,%2,%3}, [%4];"
                         : "=r"(a0), "=r"(a1), "=r"(a2r), "=r"(a3) : "r"(addr));
#pragma unroll
            for (int nt = 0; nt < 4; nt++) {
                asm volatile(
                    "mma.sync.aligned.m16n8k16.row.col.f32.f16.f16.f32 "
                    "{%0,%1,%2,%3}, {%4,%5,%6,%7}, {%8,%9}, {%0,%1,%2,%3};"
                    : "+f"(acc[mt][nt][0]), "+f"(acc[mt][nt][1]),
                      "+f"(acc[mt][nt][2]), "+f"(acc[mt][nt][3])
                    : "r"(a0), "r"(a1), "r"(a2r), "r"(a3),
                      "r"(bf[nt][0]), "r"(bf[nt][1]));
            }
        }
    }

    // ---- phase 3: silu + warp segmented merge over sorted i + red.v2 ----
    // Fragment chain: for (mt, hh), lane group q=lane>>2 holds row mt*16+hh*8+q.
    // Sorted i => equal endpoints imply equal run; Kogge-Stone suffix merge.
    int q = lane >> 2;
#pragma unroll
    for (int mt = 0; mt < 2; mt++) {
#pragma unroll
        for (int hh = 0; hh < 2; hh++) {
            int row = mt * 16 + hh * 8 + q;
            int ir = __shfl_sync(0xffffffffu, i, row);
            float vx[4], vy[4];
#pragma unroll
            for (int nt = 0; nt < 4; nt++) {
                vx[nt] = silu(acc[mt][nt][hh * 2 + 0]);
                vy[nt] = silu(acc[mt][nt][hh * 2 + 1]);
            }
#pragma unroll
            for (int d = 1; d < 8; d <<= 1) {
                int iq = __shfl_down_sync(0xffffffffu, ir, 4 * d);
                bool m = (q + d < 8) && (iq == ir);
#pragma unroll
                for (int nt = 0; nt < 4; nt++) {
                    float tx = __shfl_down_sync(0xffffffffu, vx[nt], 4 * d);
                    float ty = __shfl_down_sync(0xffffffffu, vy[nt], 4 * d);
                    if (m) { vx[nt] += tx; vy[nt] += ty; }
                }
            }
            int ip = __shfl_up_sync(0xffffffffu, ir, 4);
            bool head = (q == 0) || (ip != ir);
            if (head) {
#pragma unroll
                for (int nt = 0; nt < 4; nt++) {
                    float* d0 = mi + (size_t)ir * 32 + nt * 8 + nc;
                    asm volatile("red.global.add.v2.f32 [%0], {%1, %2};"
                                 :: "l"(d0), "f"(vx[nt]), "f"(vy[nt]) : "memory");
                }
            }
        }
    }
}

// ---------------- node MLP: feats' = silu([feats, m_i]@nW1+nb1)@nW2+nb2 ------
template <int FI>
__global__ void __launch_bounds__(256) node_kernel(
        const float* __restrict__ featsrc, int lds,
        const float* __restrict__ mi,
        const float* __restrict__ W1, const float* __restrict__ b1,
        const float* __restrict__ W2, const float* __restrict__ b2,
        float* __restrict__ featdst) {
    constexpr int CAT = FI + 32;
    __shared__ float sW1[CAT * 64];
    __shared__ float sW2[64 * 32];
    __shared__ float sb1[64];
    __shared__ float sb2s[32];
    __shared__ float scat[32][CAT];
    __shared__ float sh[32][64];
    int t = threadIdx.x;
    for (int idx = t; idx < CAT * 64; idx += 256) sW1[idx] = W1[idx];
    for (int idx = t; idx < 64 * 32; idx += 256) sW2[idx] = W2[idx];
    if (t < 64) sb1[t] = b1[t];
    if (t < 32) sb2s[t] = b2[t];

    int warp = t >> 5, lane = t & 31;
    int n0 = blockIdx.x * 32 + warp * 4;
#pragma unroll
    for (int u = 0; u < 4; u++) {
        int n = n0 + u;
        for (int idx = lane; idx < CAT; idx += 32)
            scat[warp * 4 + u][idx] = (idx < FI) ? featsrc[(size_t)n * lds + idx]
                                                 : mi[(size_t)n * 32 + (idx - FI)];
    }
    __syncthreads();

    ull h2[4];
    ull binit = pk2(sb1[lane], sb1[lane + 32]);
#pragma unroll
    for (int u = 0; u < 4; u++) h2[u] = binit;
    for (int f = 0; f < CAT; f++) {
        ull w = pk2(sW1[f * 64 + lane], sW1[f * 64 + lane + 32]);
#pragma unroll
        for (int u = 0; u < 4; u++)
            h2[u] = fma2(splat2(scat[warp * 4 + u][f]), w, h2[u]);
    }
#pragma unroll
    for (int u = 0; u < 4; u++) {
        float lo, hi; upk2(lo, hi, h2[u]);
        sh[warp * 4 + u][lane] = silu(lo);
        sh[warp * 4 + u][lane + 32] = silu(hi);
    }
    __syncwarp();

    ull o01 = splat2(sb2s[lane]);
    ull o23 = o01;
    for (int k = 0; k < 64; k++) {
        ull wv = splat2(sW2[k * 32 + lane]);
        ull x01 = pk2(sh[warp * 4 + 0][k], sh[warp * 4 + 1][k]);
        ull x23 = pk2(sh[warp * 4 + 2][k], sh[warp * 4 + 3][k]);
        o01 = fma2(x01, wv, o01);
        o23 = fma2(x23, wv, o23);
    }
    float o0, o1, o2, o3;
    upk2(o0, o1, o01);
    upk2(o2, o3, o23);
    featdst[(size_t)(n0 + 0) * 32 + lane] = o0;
    featdst[(size_t)(n0 + 1) * 32 + lane] = o1;
    featdst[(size_t)(n0 + 2) * 32 + lane] = o2;
    featdst[(size_t)(n0 + 3) * 32 + lane] = o3;
}

// ---------------- pooling ----------------------------------------------------
__global__ void pool_kernel(const float* __restrict__ feats, const int* __restrict__ batch,
                            const float* __restrict__ linW,
                            float* __restrict__ gsum, float* __restrict__ gcnt) {
    __shared__ float sw[32];
    if (threadIdx.x < 32) sw[threadIdx.x] = linW[threadIdx.x];
    __syncthreads();
    int n = blockIdx.x * blockDim.x + threadIdx.x;
    if (n >= Nn) return;
    const float4* fr = reinterpret_cast<const float4*>(feats + (size_t)n * 32);
    const float4* w4 = reinterpret_cast<const float4*>(sw);
    float s = 0.0f;
#pragma unroll
    for (int c4 = 0; c4 < 8; c4++) {
        float4 f = fr[c4];
        float4 w = w4[c4];
        s += f.x * w.x + f.y * w.y + f.z * w.z + f.w * w.w;
    }
    int g = batch[n];
    atomicAdd(&gsum[g], s);
    atomicAdd(&gcnt[g], 1.0f);
}

__global__ void finalize_kernel(const float* __restrict__ gsum, const float* __restrict__ gcnt,
                                const float* __restrict__ linb, float* __restrict__ out) {
    int g = threadIdx.x;
    if (g < Gg) out[g] = gsum[g] / fmaxf(gcnt[g], 1.0f) + linb[0];
}

// ---------------- host launcher ----------------------------------------------
extern "C" void kernel_launch(void* const* d_in, const int* in_sizes, int n_in,
                              void* d_out, int out_size) {
    const float* x = (const float*)d_in[0];
    const int* ei;
    const float* ea;
    const float* pos;
    if (in_sizes[1] == 2 * Ee) {
        ei = (const int*)d_in[1];
        ea = (const float*)d_in[2];
        pos = (const float*)d_in[3];
    } else {
        pos = (const float*)d_in[1];
        ei = (const int*)d_in[2];
        ea = (const float*)d_in[3];
    }
    const int* batch = (const int*)d_in[4];
    const float* W[26];
    for (int k = 0; k < 26; k++) W[k] = (const float*)d_in[5 + k];
    const float* linW = W[24];
    const float* linb = W[25];

    __half *P, *Q, *pk;
    float *mi, *f0, *f1, *gs, *gc;
    int *cnt, *off, *bsum, *sI, *sJ;
    float2* sAR;
    cudaGetSymbolAddress((void**)&P, g_P);
    cudaGetSymbolAddress((void**)&Q, g_Q);
    cudaGetSymbolAddress((void**)&pk, g_pack);
    cudaGetSymbolAddress((void**)&mi, g_m);
    cudaGetSymbolAddress((void**)&f0, g_f0);
    cudaGetSymbolAddress((void**)&f1, g_f1);
    cudaGetSymbolAddress((void**)&cnt, g_cnt);
    cudaGetSymbolAddress((void**)&off, g_off);
    cudaGetSymbolAddress((void**)&bsum, g_bsum);
    cudaGetSymbolAddress((void**)&sI, g_sI);
    cudaGetSymbolAddress((void**)&sJ, g_sJ);
    cudaGetSymbolAddress((void**)&sAR, g_sAR);
    cudaGetSymbolAddress((void**)&gs, g_gsum);
    cudaGetSymbolAddress((void**)&gc, g_gcnt);

    const int EB = Ee / 256;    // 6250 (256-thread kernels)
    const int EBT = Ee / 128;   // 12500 (edge tensor kernel, 128 threads)
    const int PREB = Nn / 16;   // 6250
    const int NB = Nn / 32;     // 3125
    const int PB = (Nn + 255) / 256;

    // ---- sort edges by destination i (reused by all 3 layers) ----
    cudaMemsetAsync(cnt, 0, Nn * sizeof(int));
    hist_kernel<<<EB, 256>>>(ei, cnt);
    scan1_kernel<<<NSCAN, 1024>>>(cnt, off, bsum);
    scan2_kernel<<<1, 32>>>(bsum);
    scan3_kernel<<<NSCAN, 1024>>>(off, bsum);
    scatter_kernel<<<EB, 256>>>(ei, ea, pos, off, sI, sJ, sAR);
    zero_pool_kernel<<<1, 128>>>(gs, gc);

    // ---- layer 1: FI=2, H=12 (HP=16) ----
    pack_kernel<<<1, 256>>>(W[0] + 4 * 12, W[0] + 5 * 12, W[2], 12, 16, pk);
    pre_kernel<2, 12, 16><<<PREB, 32>>>(x, 2, W[0], W[1], P, Q);
    cudaMemsetAsync(mi, 0, (size_t)Nn * 32 * sizeof(float));
    edge_kernel<12, 16><<<EBT, 128>>>(sI, sJ, sAR, P, Q, pk, W[3], mi);
    node_kernel<2><<<NB, 256>>>(x, 2, mi, W[4], W[5], W[6], W[7], f0);

    // ---- layer 2: FI=32, H=132 (HP=144) ----
    pack_kernel<<<1, 256>>>(W[8] + 64 * 132, W[8] + 65 * 132, W[10], 132, 144, pk);
    pre_kernel<32, 132, 144><<<PREB, 160>>>(f0, 32, W[8], W[9], P, Q);
    cudaMemsetAsync(mi, 0, (size_t)Nn * 32 * sizeof(float));
    edge_kernel<132, 144><<<EBT, 128>>>(sI, sJ, sAR, P, Q, pk, W[11], mi);
    node_kernel<32><<<NB, 256>>>(f0, 32, mi, W[12], W[13], W[14], W[15], f1);

    // ---- layer 3: FI=32, H=132 (HP=144) ----
    pack_kernel<<<1, 256>>>(W[16] + 64 * 132, W[16] + 65 * 132, W[18], 132, 144, pk);
    pre_kernel<32, 132, 144><<<PREB, 160>>>(f1, 32, W[16], W[17], P, Q);
    cudaMemsetAsync(mi, 0, (size_t)Nn * 32 * sizeof(float));
    edge_kernel<132, 144><<<EBT, 128>>>(sI, sJ, sAR, P, Q, pk, W[19], mi);
    node_kernel<32><<<NB, 256>>>(f1, 32, mi, W[20], W[21], W[22], W[23], f0);

    // ---- pool + head ----
    pool_kernel<<<PB, 256>>>(f0, batch, linW, gs, gc);
    finalize_kernel<<<1, 128>>>(gs, gc, linb, (float*)d_out);
}